// round 9
// baseline (speedup 1.0000x reference)
#include <cuda_runtime.h>
#include <cuda_bf16.h>
#include <cstdint>

// ---------------------------------------------------------------------------
// Shapes
// ---------------------------------------------------------------------------
#define BS      32
#define NUM_R   10
#define SL_Q    20
#define SL_H    40
#define WE      300
#define LSTM    1024
#define BILSTM  2048
#define FEATD   600

#define MQ (BS * SL_Q)          // 640
#define MH (BS * NUM_R * SL_H)  // 12800
#define KW8 (BILSTM / 4)        // 512 words of 4 int8 per row
#define NWROWS (4 * LSTM)       // 4096 quantized weight rows

// ---------------------------------------------------------------------------
// Scratch (device globals)
// ---------------------------------------------------------------------------
__device__ float g_qfeat[MQ * LSTM];
__device__ float g_hfeat[MH * LSTM];
__device__ float g_topic[BS * NUM_R * SL_Q * WE];
__device__ float g_feat [MQ * FEATD];

__device__ float g_wt[NWROWS * BILSTM];          // transposed weights fp32
// int8 limbs packed 4/word
__device__ uint32_t g_xq1[MQ * KW8], g_xq2[MQ * KW8];
__device__ uint32_t g_xh1[MH * KW8], g_xh2[MH * KW8];
__device__ uint32_t g_w1[NWROWS * KW8], g_w2[NWROWS * KW8];
__device__ float g_xsc_q[MQ], g_xsc_h[MH], g_wsc[NWROWS];

// ---------------------------------------------------------------------------
// Helpers
// ---------------------------------------------------------------------------
__device__ __forceinline__ float leaky(float x) {
    return x >= 0.f ? x : 0.01f * x;
}

__device__ __forceinline__ void cpasync16(uint32_t dst, const void* src) {
    asm volatile("cp.async.cg.shared.global [%0], [%1], 16;"
                 :: "r"(dst), "l"(src) : "memory");
}

__device__ __forceinline__ void imma32(int c[4], const uint32_t a[4],
                                       uint32_t b0, uint32_t b1) {
    asm volatile(
        "mma.sync.aligned.m16n8k32.row.col.s32.s8.s8.s32 "
        "{%0,%1,%2,%3},{%4,%5,%6,%7},{%8,%9},{%0,%1,%2,%3};"
        : "+r"(c[0]), "+r"(c[1]), "+r"(c[2]), "+r"(c[3])
        : "r"(a[0]), "r"(a[1]), "r"(a[2]), "r"(a[3]), "r"(b0), "r"(b1));
}

__device__ __forceinline__ void ldsm_x4(uint32_t& r0, uint32_t& r1,
                                        uint32_t& r2, uint32_t& r3, uint32_t addr) {
    asm volatile("ldmatrix.sync.aligned.m8n8.x4.shared.b16 {%0,%1,%2,%3}, [%4];"
                 : "=r"(r0), "=r"(r1), "=r"(r2), "=r"(r3) : "r"(addr));
}

// ---------------------------------------------------------------------------
// Precompute 1: transpose 4 weight matrices [2048,1024] -> g_wt [4][1024][2048]
// ---------------------------------------------------------------------------
__global__ __launch_bounds__(256)
void wt_transpose(const float* __restrict__ W0, const float* __restrict__ W1,
                  const float* __restrict__ W2, const float* __restrict__ W3,
                  float* __restrict__ wt) {
    const float* W = (blockIdx.z == 0) ? W0 : (blockIdx.z == 1) ? W1
                    : (blockIdx.z == 2) ? W2 : W3;
    float* dst = wt + (size_t)blockIdx.z * LSTM * BILSTM;
    __shared__ float t[32][33];
    int k0 = blockIdx.x * 32, n0 = blockIdx.y * 32;
    int tx = threadIdx.x & 31, ty = threadIdx.x >> 5;
#pragma unroll
    for (int j = 0; j < 4; j++)
        t[ty + 8 * j][tx] = W[(size_t)(k0 + ty + 8 * j) * LSTM + n0 + tx];
    __syncthreads();
#pragma unroll
    for (int j = 0; j < 4; j++)
        dst[(size_t)(n0 + ty + 8 * j) * BILSTM + k0 + tx] = t[tx][ty + 8 * j];
}

// ---------------------------------------------------------------------------
// Precompute 2: per-row 2-limb int8 quantization (one block per row of 2048)
// rows: [0,MQ)=Xq, [MQ,MQ+MH)=Xh, rest = Wt
// ---------------------------------------------------------------------------
__global__ __launch_bounds__(256)
void quant_rows(const float* __restrict__ xq, uint32_t* __restrict__ q1,
                uint32_t* __restrict__ q2, float* __restrict__ qsc,
                const float* __restrict__ xh, uint32_t* __restrict__ h1,
                uint32_t* __restrict__ h2, float* __restrict__ hsc,
                const float* __restrict__ wt, uint32_t* __restrict__ w1,
                uint32_t* __restrict__ w2, float* __restrict__ wsc) {
    int rb = blockIdx.x;
    const float* src; uint32_t *d1, *d2; float* dsc; int row;
    if (rb < MQ)           { src = xq; d1 = q1; d2 = q2; dsc = qsc; row = rb; }
    else if (rb < MQ + MH) { src = xh; d1 = h1; d2 = h2; dsc = hsc; row = rb - MQ; }
    else                   { src = wt; d1 = w1; d2 = w2; dsc = wsc; row = rb - MQ - MH; }

    const float* p = src + (size_t)row * BILSTM;
    const int t = threadIdx.x;
    float4 v0 = ((const float4*)p)[t * 2];
    float4 v1 = ((const float4*)p)[t * 2 + 1];
    float vals[8] = {v0.x, v0.y, v0.z, v0.w, v1.x, v1.y, v1.z, v1.w};

    float m = 0.f;
#pragma unroll
    for (int i = 0; i < 8; i++) m = fmaxf(m, fabsf(vals[i]));
#pragma unroll
    for (int o = 16; o; o >>= 1) m = fmaxf(m, __shfl_xor_sync(0xFFFFFFFFu, m, o));
    __shared__ float wmx[8];
    if ((t & 31) == 0) wmx[t >> 5] = m;
    __syncthreads();
    float mv = 1e-30f;
#pragma unroll
    for (int i = 0; i < 8; i++) mv = fmaxf(mv, wmx[i]);
    const float inv = 127.0f / mv;
    if (t == 0) dsc[row] = mv * (1.0f / 127.0f);

    uint32_t p1[2] = {0, 0}, p2[2] = {0, 0};
#pragma unroll
    for (int i = 0; i < 8; i++) {
        float q  = vals[i] * inv;
        float a1 = rintf(q);
        float a2 = rintf((q - a1) * 128.f);
        uint32_t b1 = (uint32_t)(uint8_t)(int8_t)(int)a1;
        uint32_t b2 = (uint32_t)(uint8_t)(int8_t)(int)a2;
        p1[i >> 2] |= b1 << ((i & 3) * 8);
        p2[i >> 2] |= b2 << ((i & 3) * 8);
    }
    size_t ow = (size_t)row * KW8 + t * 2;
    d1[ow] = p1[0]; d1[ow + 1] = p1[1];
    d2[ow] = p2[0]; d2[ow + 1] = p2[1];
}

// ---------------------------------------------------------------------------
// Gated transform via int8 2-limb imma:
//   pre = scA[m]*scW[n]*(HH + MID/128);  out = tanh(preY+by)*leaky(preG+bg)
// Tile 128x64, K-chunk 128 (int8: 128B rows, SW128 swizzle), double-buffered.
// Grid (16 n-tiles FAST, 105 m-tiles: 0-4 = q, 5-104 = h).
// 8 warps: 2m x 4n, warp tile 64x16 (mt=4, nt=2).
// ---------------------------------------------------------------------------
#define TBM 128
#define TBN 64
#define NCH2 16
#define CH2_BYTES 65536
#define SM_CTRL 1024
#define GG2_SMEM (SM_CTRL + 2 * CH2_BYTES)   // 132096

__global__ __launch_bounds__(256, 1)
void gated_gemm_i8(const uint32_t* __restrict__ xq1, const uint32_t* __restrict__ xq2,
                   const float* __restrict__ xscq,
                   const uint32_t* __restrict__ xh1, const uint32_t* __restrict__ xh2,
                   const float* __restrict__ xsch,
                   const uint32_t* __restrict__ w1, const uint32_t* __restrict__ w2,
                   const float* __restrict__ wsc,
                   const float* __restrict__ qby, const float* __restrict__ qbg,
                   const float* __restrict__ hby, const float* __restrict__ hbg,
                   float* __restrict__ qout, float* __restrict__ hout) {
    extern __shared__ char smem[];
    const uint32_t smem_base = (uint32_t)__cvta_generic_to_shared(smem);
    const int tid  = threadIdx.x;
    const int warp = tid >> 5;
    const int lane = tid & 31;
    const int n0 = blockIdx.x * TBN;

    const bool isq = (blockIdx.y < 5);
    const int m0 = isq ? blockIdx.y * TBM : (blockIdx.y - 5) * TBM;
    const uint32_t* X1 = isq ? xq1 : xh1;
    const uint32_t* X2 = isq ? xq2 : xh2;
    const float* scA = isq ? xscq : xsch;
    const int yrow = (isq ? 0 : 2) * LSTM;   // weight-matrix row offsets
    const int grow = (isq ? 1 : 3) * LSTM;
    const uint32_t* Wy1 = w1 + (size_t)yrow * KW8;
    const uint32_t* Wy2 = w2 + (size_t)yrow * KW8;
    const uint32_t* Wg1 = w1 + (size_t)grow * KW8;
    const uint32_t* Wg2 = w2 + (size_t)grow * KW8;
    const float* scY = wsc + yrow;
    const float* scG = wsc + grow;
    const float* by = isq ? qby : hby;
    const float* bg = isq ? qbg : hbg;
    float* out = isq ? qout : hout;

    // chunk loader: A1,A2 (128 rows x 128B) + Y1,Y2,G1,G2 (64 rows x 128B)
    auto load_chunk = [&](int c) {
        const uint32_t bb = smem_base + SM_CTRL + (uint32_t)(c & 1) * CH2_BYTES;
        const int kwc = c * 32;   // word offset of chunk within row
#pragma unroll
        for (int i = 0; i < 16; i++) {
            const uint32_t* s; int rb, idx; uint32_t doff; const uint32_t* basep;
            if (i < 4)       { basep = X1;  rb = m0; doff = 0;     idx = tid + i * 256; }
            else if (i < 8)  { basep = X2;  rb = m0; doff = 16384; idx = tid + (i - 4) * 256; }
            else if (i < 10) { basep = Wy1; rb = n0; doff = 32768; idx = tid + (i - 8) * 256; }
            else if (i < 12) { basep = Wy2; rb = n0; doff = 40960; idx = tid + (i - 10) * 256; }
            else if (i < 14) { basep = Wg1; rb = n0; doff = 49152; idx = tid + (i - 12) * 256; }
            else             { basep = Wg2; rb = n0; doff = 57344; idx = tid + (i - 14) * 256; }
            const int row = idx >> 3, seg = idx & 7;
            const void* src = basep + (size_t)(rb + row) * KW8 + kwc + seg * 4;
            uint32_t bo = (uint32_t)(row * 128 + seg * 16);
            cpasync16(bb + doff + (bo ^ ((bo >> 3) & 0x70)), src);
        }
        asm volatile("cp.async.commit_group;" ::: "memory");
    };

    // warp / lane geometry (identical to proven bf16 wiring)
    const int wm = (warp >> 2) * 64;       // 0 / 64
    const int wn = (warp & 3) * 16;        // 0,16,32,48
    int rowA[4], swzA[4];
#pragma unroll
    for (int mt = 0; mt < 4; mt++) {
        rowA[mt] = wm + 16 * mt + (lane & 15);
        swzA[mt] = rowA[mt] & 7;
    }
    const int kselA = lane >> 4;
    const int rowB = wn + (lane & 7) + ((lane & 16) >> 1);
    const int swzB = rowB & 7;
    const int kselB = (lane >> 3) & 1;

    int accYH[4][2][4] = {}, accYM[4][2][4] = {};
    int accGH[4][2][4] = {}, accGM[4][2][4] = {};

    load_chunk(0);
    for (int c = 0; c < NCH2; c++) {
        if (c + 1 < NCH2) {
            load_chunk(c + 1);
            asm volatile("cp.async.wait_group 1;" ::: "memory");
        } else {
            asm volatile("cp.async.wait_group 0;" ::: "memory");
        }
        __syncthreads();
        const uint32_t bb = smem_base + SM_CTRL + (uint32_t)(c & 1) * CH2_BYTES;

#pragma unroll
        for (int ks = 0; ks < 4; ks++) {
            const uint32_t gA = (uint32_t)(2 * ks + kselA);
            const uint32_t gB = (uint32_t)(2 * ks + kselB);

            uint32_t a1f[4][4], a2f[4][4];
#pragma unroll
            for (int mt = 0; mt < 4; mt++) {
                uint32_t off = (uint32_t)(rowA[mt] * 128) + ((gA ^ (uint32_t)swzA[mt]) << 4);
                ldsm_x4(a1f[mt][0], a1f[mt][1], a1f[mt][2], a1f[mt][3], bb + off);
                ldsm_x4(a2f[mt][0], a2f[mt][1], a2f[mt][2], a2f[mt][3], bb + 16384 + off);
            }
            const uint32_t offB = (uint32_t)(rowB * 128) + ((gB ^ (uint32_t)swzB) << 4);

            // ---- Y branch ----
            {
                uint32_t y1[2][2], y2[2][2];
                ldsm_x4(y1[0][0], y1[0][1], y1[1][0], y1[1][1], bb + 32768 + offB);
                ldsm_x4(y2[0][0], y2[0][1], y2[1][0], y2[1][1], bb + 40960 + offB);
#pragma unroll
                for (int nt = 0; nt < 2; nt++)
#pragma unroll
                    for (int mt = 0; mt < 4; mt++) {
                        imma32(accYH[mt][nt], a1f[mt], y1[nt][0], y1[nt][1]);
                        imma32(accYM[mt][nt], a1f[mt], y2[nt][0], y2[nt][1]);
                        imma32(accYM[mt][nt], a2f[mt], y1[nt][0], y1[nt][1]);
                    }
            }
            // ---- G branch ----
            {
                uint32_t gg1[2][2], gg2[2][2];
                ldsm_x4(gg1[0][0], gg1[0][1], gg1[1][0], gg1[1][1], bb + 49152 + offB);
                ldsm_x4(gg2[0][0], gg2[0][1], gg2[1][0], gg2[1][1], bb + 57344 + offB);
#pragma unroll
                for (int nt = 0; nt < 2; nt++)
#pragma unroll
                    for (int mt = 0; mt < 4; mt++) {
                        imma32(accGH[mt][nt], a1f[mt], gg1[nt][0], gg1[nt][1]);
                        imma32(accGM[mt][nt], a1f[mt], gg2[nt][0], gg2[nt][1]);
                        imma32(accGM[mt][nt], a2f[mt], gg1[nt][0], gg1[nt][1]);
                    }
            }
        }
        __syncthreads();
    }

    // ---- epilogue: scales, bias, activations ----
    const int ar = lane >> 2;
    const int ac = lane & 3;
    const float INV128 = 0.0078125f;
#pragma unroll
    for (int mt = 0; mt < 4; mt++) {
        int gr = m0 + wm + 16 * mt + ar;
        float sA0 = scA[gr], sA1 = scA[gr + 8];
#pragma unroll
        for (int nt = 0; nt < 2; nt++) {
            int gc = n0 + wn + 8 * nt + 2 * ac;
            float sy0 = scY[gc], sy1 = scY[gc + 1];
            float sg0 = scG[gc], sg1 = scG[gc + 1];
            float b_y0 = by[gc], b_y1 = by[gc + 1];
            float b_g0 = bg[gc], b_g1 = bg[gc + 1];

            float y00 = sA0 * sy0 * ((float)accYH[mt][nt][0] + (float)accYM[mt][nt][0] * INV128);
            float y01 = sA0 * sy1 * ((float)accYH[mt][nt][1] + (float)accYM[mt][nt][1] * INV128);
            float y10 = sA1 * sy0 * ((float)accYH[mt][nt][2] + (float)accYM[mt][nt][2] * INV128);
            float y11 = sA1 * sy1 * ((float)accYH[mt][nt][3] + (float)accYM[mt][nt][3] * INV128);
            float g00 = sA0 * sg0 * ((float)accGH[mt][nt][0] + (float)accGM[mt][nt][0] * INV128);
            float g01 = sA0 * sg1 * ((float)accGH[mt][nt][1] + (float)accGM[mt][nt][1] * INV128);
            float g10 = sA1 * sg0 * ((float)accGH[mt][nt][2] + (float)accGM[mt][nt][2] * INV128);
            float g11 = sA1 * sg1 * ((float)accGH[mt][nt][3] + (float)accGM[mt][nt][3] * INV128);

            float v00 = tanhf(y00 + b_y0) * leaky(g00 + b_g0);
            float v01 = tanhf(y01 + b_y1) * leaky(g01 + b_g1);
            float v10 = tanhf(y10 + b_y0) * leaky(g10 + b_g0);
            float v11 = tanhf(y11 + b_y1) * leaky(g11 + b_g1);

            *(float2*)&out[(size_t)gr * LSTM + gc]       = make_float2(v00, v01);
            *(float2*)&out[(size_t)(gr + 8) * LSTM + gc] = make_float2(v10, v11);
        }
    }
}

// ---------------------------------------------------------------------------
// Kernel 2: per-(b,r) attention block (proven)
// ---------------------------------------------------------------------------
#define CK 64
#define QS_STRIDE 65
#define HS_STRIDE 65
#define ATTN_SMEM_FLOATS (12000 + SL_Q * QS_STRIDE + SL_H * HS_STRIDE + SL_Q * SL_H)

__global__ __launch_bounds__(256)
void attn_kernel(const float* __restrict__ qf, const float* __restrict__ hf,
                 const float* __restrict__ emb, const float* __restrict__ notpad,
                 const float* __restrict__ cms, float* __restrict__ topic) {
    extern __shared__ float sm[];
    float* emb_s = sm;
    float* qs = emb_s + 12000;
    float* hs = qs + SL_Q * QS_STRIDE;
    float* S  = hs + SL_H * HS_STRIDE;

    const int t = threadIdx.x;
    const int r = blockIdx.x;
    const int b = blockIdx.y;
    const int br = b * NUM_R + r;

    for (int i = t; i < SL_H * WE; i += 256)
        emb_s[i] = emb[(size_t)br * (SL_H * WE) + i];

    const int q2 = t / 20;
    const int h2 = t % 20;
    float acc00 = 0.f, acc01 = 0.f, acc10 = 0.f, acc11 = 0.f;

    for (int kc = 0; kc < LSTM; kc += CK) {
        for (int i = t; i < SL_Q * CK; i += 256) {
            int row = i >> 6, col = i & 63;
            qs[row * QS_STRIDE + col] = qf[(size_t)(b * SL_Q + row) * LSTM + kc + col];
        }
        for (int i = t; i < SL_H * CK; i += 256) {
            int row = i >> 6, col = i & 63;
            hs[row * HS_STRIDE + col] = hf[(size_t)(br * SL_H + row) * LSTM + kc + col];
        }
        __syncthreads();
        if (t < 200) {
            const float* q0p = &qs[(2 * q2)     * QS_STRIDE];
            const float* q1p = &qs[(2 * q2 + 1) * QS_STRIDE];
            const float* h0p = &hs[(2 * h2)     * HS_STRIDE];
            const float* h1p = &hs[(2 * h2 + 1) * HS_STRIDE];
#pragma unroll 8
            for (int k = 0; k < CK; k++) {
                float q0 = q0p[k], q1 = q1p[k];
                float h0 = h0p[k], h1 = h1p[k];
                acc00 += q0 * h0; acc01 += q0 * h1;
                acc10 += q1 * h0; acc11 += q1 * h1;
            }
        }
        __syncthreads();
    }

    if (t < 200) {
        S[(2 * q2)     * SL_H + 2 * h2]     = acc00;
        S[(2 * q2)     * SL_H + 2 * h2 + 1] = acc01;
        S[(2 * q2 + 1) * SL_H + 2 * h2]     = acc10;
        S[(2 * q2 + 1) * SL_H + 2 * h2 + 1] = acc11;
    }
    __syncthreads();

    if (t < SL_Q) {
        float mx = -1e30f;
        for (int h = 0; h < SL_H; h++) {
            float m = notpad[(size_t)br * SL_H + h];
            float s = S[t * SL_H + h] * m + (m - 1.0f) * 10000.0f;
            S[t * SL_H + h] = s;
            mx = fmaxf(mx, s);
        }
        float den = 0.f;
        for (int h = 0; h < SL_H; h++) {
            float e = expf(S[t * SL_H + h] - mx);
            S[t * SL_H + h] = e;
            den += e;
        }
        float inv = 1.0f / den;
        for (int h = 0; h < SL_H; h++) S[t * SL_H + h] *= inv;
    }
    __syncthreads();

    const float c = cms[br];
    for (int o = t; o < SL_Q * WE; o += 256) {
        int q = o / WE, e = o % WE;
        float s = 0.f;
#pragma unroll 8
        for (int h = 0; h < SL_H; h++)
            s += S[q * SL_H + h] * emb_s[h * WE + e];
        topic[(size_t)(br * SL_Q + q) * WE + e] = s * c;
    }
}

// ---------------------------------------------------------------------------
// Kernel 3: feat = concat(q_embed, sum_r topic)
// ---------------------------------------------------------------------------
__global__ __launch_bounds__(256)
void feat_build(const float* __restrict__ q_embed, const float* __restrict__ topic,
                float* __restrict__ feat) {
    int idx = blockIdx.x * 256 + threadIdx.x;
    int m  = idx / FEATD;
    int e2 = idx % FEATD;
    float v;
    if (e2 < WE) {
        v = q_embed[(size_t)m * WE + e2];
    } else {
        int e = e2 - WE;
        int b = m / SL_Q, q = m % SL_Q;
        v = 0.f;
#pragma unroll
        for (int r = 0; r < NUM_R; r++)
            v += topic[(size_t)((b * NUM_R + r) * SL_Q + q) * WE + e];
    }
    feat[idx] = v;
}

// ---------------------------------------------------------------------------
// Kernel 4: out = sigmoid(feat@Wg + bg) * feat
// ---------------------------------------------------------------------------
#define FBM 64
#define FBN 64
#define FBK 16

__global__ __launch_bounds__(256)
void final_gemm(const float* __restrict__ feat, const float* __restrict__ Wg,
                const float* __restrict__ bg, float* __restrict__ out) {
    __shared__ float Fs[FBM][FBK + 1];
    __shared__ float Bsm[FBK][FBN + 1];

    const int t = threadIdx.x;
    const int ty = t >> 4, tx = t & 15;
    const int m0 = blockIdx.x * FBM;
    const int n0 = blockIdx.y * FBN;

    float acc[4][4];
#pragma unroll
    for (int i = 0; i < 4; i++)
#pragma unroll
        for (int j = 0; j < 4; j++) acc[i][j] = 0.f;

    for (int k0 = 0; k0 < FEATD; k0 += FBK) {
        for (int i = t; i < FBM * FBK; i += 256) {
            int r = i >> 4, c = i & 15;
            int k = k0 + c;
            Fs[r][c] = (k < FEATD) ? feat[(size_t)(m0 + r) * FEATD + k] : 0.f;
        }
        for (int i = t; i < FBK * FBN; i += 256) {
            int r = i >> 6, c = i & 63;
            int k = k0 + r, n = n0 + c;
            Bsm[r][c] = (k < FEATD && n < FEATD) ? Wg[(size_t)k * FEATD + n] : 0.f;
        }
        __syncthreads();
#pragma unroll
        for (int k = 0; k < FBK; k++) {
            float a[4], bb[4];
#pragma unroll
            for (int i = 0; i < 4; i++) a[i]  = Fs[ty * 4 + i][k];
#pragma unroll
            for (int j = 0; j < 4; j++) bb[j] = Bsm[k][tx * 4 + j];
#pragma unroll
            for (int i = 0; i < 4; i++)
#pragma unroll
                for (int j = 0; j < 4; j++) acc[i][j] += a[i] * bb[j];
        }
        __syncthreads();
    }

#pragma unroll
    for (int i = 0; i < 4; i++) {
        int row = m0 + ty * 4 + i;
#pragma unroll
        for (int j = 0; j < 4; j++) {
            int col = n0 + tx * 4 + j;
            if (col < FEATD) {
                float v = acc[i][j] + bg[col];
                float g = 1.0f / (1.0f + expf(-v));
                out[(size_t)row * FEATD + col] = g * feat[(size_t)row * FEATD + col];
            }
        }
    }
}

// ---------------------------------------------------------------------------
// Host launcher
// ---------------------------------------------------------------------------
extern "C" void kernel_launch(void* const* d_in, const int* in_sizes, int n_in,
                              void* d_out, int out_size) {
    const float* q_embed = (const float*)d_in[0];
    const float* q_enc   = (const float*)d_in[1];
    const float* h_embed = (const float*)d_in[2];
    const float* h_enc   = (const float*)d_in[3];
    const float* notpad  = (const float*)d_in[4];
    const float* cms     = (const float*)d_in[5];
    const float* Wq_y = (const float*)d_in[6];
    const float* bq_y = (const float*)d_in[7];
    const float* Wq_g = (const float*)d_in[8];
    const float* bq_g = (const float*)d_in[9];
    const float* Wh_y = (const float*)d_in[10];
    const float* bh_y = (const float*)d_in[11];
    const float* Wh_g = (const float*)d_in[12];
    const float* bh_g = (const float*)d_in[13];
    const float* Wg   = (const float*)d_in[14];
    const float* bg   = (const float*)d_in[15];
    float* out = (float*)d_out;

    float *qf, *hf, *topic, *feat, *wt;
    cudaGetSymbolAddress((void**)&qf,    g_qfeat);
    cudaGetSymbolAddress((void**)&hf,    g_hfeat);
    cudaGetSymbolAddress((void**)&topic, g_topic);
    cudaGetSymbolAddress((void**)&feat,  g_feat);
    cudaGetSymbolAddress((void**)&wt,    g_wt);

    uint32_t *xq1, *xq2, *xh1, *xh2, *w1, *w2;
    float *xscq, *xsch, *wsc;
    cudaGetSymbolAddress((void**)&xq1, g_xq1);
    cudaGetSymbolAddress((void**)&xq2, g_xq2);
    cudaGetSymbolAddress((void**)&xh1, g_xh1);
    cudaGetSymbolAddress((void**)&xh2, g_xh2);
    cudaGetSymbolAddress((void**)&w1,  g_w1);
    cudaGetSymbolAddress((void**)&w2,  g_w2);
    cudaGetSymbolAddress((void**)&xscq, g_xsc_q);
    cudaGetSymbolAddress((void**)&xsch, g_xsc_h);
    cudaGetSymbolAddress((void**)&wsc,  g_wsc);

    cudaFuncSetAttribute(gated_gemm_i8, cudaFuncAttributeMaxDynamicSharedMemorySize,
                         GG2_SMEM);
    const int attn_smem = ATTN_SMEM_FLOATS * (int)sizeof(float);
    cudaFuncSetAttribute(attn_kernel, cudaFuncAttributeMaxDynamicSharedMemorySize,
                         attn_smem);

    // 0: transpose weights (order: Wq_y, Wq_g, Wh_y, Wh_g)
    wt_transpose<<<dim3(BILSTM / 32, LSTM / 32, 4), 256>>>(Wq_y, Wq_g, Wh_y, Wh_g, wt);

    // 1: fused row quantization (Xq, Xh, Wt)
    quant_rows<<<MQ + MH + NWROWS, 256>>>(q_enc, xq1, xq2, xscq,
                                          h_enc, xh1, xh2, xsch,
                                          wt, w1, w2, wsc);

    // 2: merged gated transforms (int8 imma)
    gated_gemm_i8<<<dim3(LSTM / TBN, 5 + MH / TBM), 256, GG2_SMEM>>>(
        xq1, xq2, xscq, xh1, xh2, xsch, w1, w2, wsc,
        bq_y, bq_g, bh_y, bh_g, qf, hf);

    // 3: attention + topic
    attn_kernel<<<dim3(NUM_R, BS), 256, attn_smem>>>(qf, hf, h_embed, notpad, cms, topic);

    // 4: concat + reduce over r
    feat_build<<<(MQ * FEATD) / 256, 256>>>(q_embed, topic, feat);

    // 5: final gated output
    final_gemm<<<dim3(MQ / FBM, (FEATD + FBN - 1) / FBN), 256>>>(feat, Wg, bg, out);
}

// round 10
// speedup vs baseline: 1.0191x; 1.0191x over previous
#include <cuda_runtime.h>
#include <cuda_bf16.h>
#include <cstdint>

// ---------------------------------------------------------------------------
// Shapes
// ---------------------------------------------------------------------------
#define BS      32
#define NUM_R   10
#define SL_Q    20
#define SL_H    40
#define WE      300
#define LSTM    1024
#define BILSTM  2048
#define FEATD   600

#define MQ (BS * SL_Q)          // 640
#define MH (BS * NUM_R * SL_H)  // 12800
#define KW8 (BILSTM / 4)        // 512 words of 4 int8 per row
#define NWROWS (4 * LSTM)       // 4096 quantized weight rows

// ---------------------------------------------------------------------------
// Scratch (device globals)
// ---------------------------------------------------------------------------
__device__ float g_qfeat[MQ * LSTM];
__device__ float g_hfeat[MH * LSTM];
__device__ float g_topic[BS * NUM_R * SL_Q * WE];
__device__ float g_feat [MQ * FEATD];

__device__ float g_wt[NWROWS * BILSTM];          // transposed weights fp32
__device__ uint32_t g_xq1[MQ * KW8], g_xq2[MQ * KW8];
__device__ uint32_t g_xh1[MH * KW8], g_xh2[MH * KW8];
__device__ uint32_t g_w1[NWROWS * KW8], g_w2[NWROWS * KW8];
__device__ float g_xsc_q[MQ], g_xsc_h[MH], g_wsc[NWROWS];

// ---------------------------------------------------------------------------
// Helpers
// ---------------------------------------------------------------------------
__device__ __forceinline__ float leaky(float x) {
    return x >= 0.f ? x : 0.01f * x;
}

__device__ __forceinline__ void cpasync16(uint32_t dst, const void* src) {
    asm volatile("cp.async.cg.shared.global [%0], [%1], 16;"
                 :: "r"(dst), "l"(src) : "memory");
}

__device__ __forceinline__ void imma32(int c[4], const uint32_t a[4],
                                       uint32_t b0, uint32_t b1) {
    asm volatile(
        "mma.sync.aligned.m16n8k32.row.col.s32.s8.s8.s32 "
        "{%0,%1,%2,%3},{%4,%5,%6,%7},{%8,%9},{%0,%1,%2,%3};"
        : "+r"(c[0]), "+r"(c[1]), "+r"(c[2]), "+r"(c[3])
        : "r"(a[0]), "r"(a[1]), "r"(a[2]), "r"(a[3]), "r"(b0), "r"(b1));
}

__device__ __forceinline__ void ldsm_x4(uint32_t& r0, uint32_t& r1,
                                        uint32_t& r2, uint32_t& r3, uint32_t addr) {
    asm volatile("ldmatrix.sync.aligned.m8n8.x4.shared.b16 {%0,%1,%2,%3}, [%4];"
                 : "=r"(r0), "=r"(r1), "=r"(r2), "=r"(r3) : "r"(addr));
}

// ---------------------------------------------------------------------------
// Precompute 1: transpose 4 weight matrices [2048,1024] -> g_wt [4][1024][2048]
// ---------------------------------------------------------------------------
__global__ __launch_bounds__(256)
void wt_transpose(const float* __restrict__ W0, const float* __restrict__ W1,
                  const float* __restrict__ W2, const float* __restrict__ W3,
                  float* __restrict__ wt) {
    const float* W = (blockIdx.z == 0) ? W0 : (blockIdx.z == 1) ? W1
                    : (blockIdx.z == 2) ? W2 : W3;
    float* dst = wt + (size_t)blockIdx.z * LSTM * BILSTM;
    __shared__ float t[32][33];
    int k0 = blockIdx.x * 32, n0 = blockIdx.y * 32;
    int tx = threadIdx.x & 31, ty = threadIdx.x >> 5;
#pragma unroll
    for (int j = 0; j < 4; j++)
        t[ty + 8 * j][tx] = W[(size_t)(k0 + ty + 8 * j) * LSTM + n0 + tx];
    __syncthreads();
#pragma unroll
    for (int j = 0; j < 4; j++)
        dst[(size_t)(n0 + ty + 8 * j) * BILSTM + k0 + tx] = t[tx][ty + 8 * j];
}

// ---------------------------------------------------------------------------
// Precompute 2: per-row 2-limb int8 quantization (proven in R9)
// ---------------------------------------------------------------------------
__global__ __launch_bounds__(256)
void quant_rows(const float* __restrict__ xq, uint32_t* __restrict__ q1,
                uint32_t* __restrict__ q2, float* __restrict__ qsc,
                const float* __restrict__ xh, uint32_t* __restrict__ h1,
                uint32_t* __restrict__ h2, float* __restrict__ hsc,
                const float* __restrict__ wt, uint32_t* __restrict__ w1,
                uint32_t* __restrict__ w2, float* __restrict__ wsc) {
    int rb = blockIdx.x;
    const float* src; uint32_t *d1, *d2; float* dsc; int row;
    if (rb < MQ)           { src = xq; d1 = q1; d2 = q2; dsc = qsc; row = rb; }
    else if (rb < MQ + MH) { src = xh; d1 = h1; d2 = h2; dsc = hsc; row = rb - MQ; }
    else                   { src = wt; d1 = w1; d2 = w2; dsc = wsc; row = rb - MQ - MH; }

    const float* p = src + (size_t)row * BILSTM;
    const int t = threadIdx.x;
    float4 v0 = ((const float4*)p)[t * 2];
    float4 v1 = ((const float4*)p)[t * 2 + 1];
    float vals[8] = {v0.x, v0.y, v0.z, v0.w, v1.x, v1.y, v1.z, v1.w};

    float m = 0.f;
#pragma unroll
    for (int i = 0; i < 8; i++) m = fmaxf(m, fabsf(vals[i]));
#pragma unroll
    for (int o = 16; o; o >>= 1) m = fmaxf(m, __shfl_xor_sync(0xFFFFFFFFu, m, o));
    __shared__ float wmx[8];
    if ((t & 31) == 0) wmx[t >> 5] = m;
    __syncthreads();
    float mv = 1e-30f;
#pragma unroll
    for (int i = 0; i < 8; i++) mv = fmaxf(mv, wmx[i]);
    const float inv = 127.0f / mv;
    if (t == 0) dsc[row] = mv * (1.0f / 127.0f);

    uint32_t p1[2] = {0, 0}, p2[2] = {0, 0};
#pragma unroll
    for (int i = 0; i < 8; i++) {
        float q  = vals[i] * inv;
        float a1 = rintf(q);
        float a2 = rintf((q - a1) * 128.f);
        uint32_t b1 = (uint32_t)(uint8_t)(int8_t)(int)a1;
        uint32_t b2 = (uint32_t)(uint8_t)(int8_t)(int)a2;
        p1[i >> 2] |= b1 << ((i & 3) * 8);
        p2[i >> 2] |= b2 << ((i & 3) * 8);
    }
    size_t ow = (size_t)row * KW8 + t * 2;
    d1[ow] = p1[0]; d1[ow + 1] = p1[1];
    d2[ow] = p2[0]; d2[ow + 1] = p2[1];
}

// ---------------------------------------------------------------------------
// Gated transform, int8 2-limb imma, register-budgeted tiling:
// Tile 128x64, K-chunk 128, 512 threads / 16 warps (4m x 4n), warp tile 32x16.
// accs: 4 groups x [2mt][2nt][4] = 64 int regs.
// Grid (16 n-tiles FAST, 105 m-tiles: 0-4 = q, 5-104 = h).
// ---------------------------------------------------------------------------
#define TBM 128
#define TBN 64
#define NCH2 16
#define CH2_BYTES 65536
#define SM_CTRL 1024
#define GG2_SMEM (SM_CTRL + 2 * CH2_BYTES)   // 132096

__global__ __launch_bounds__(512, 1)
void gated_gemm_i8(const uint32_t* __restrict__ xq1, const uint32_t* __restrict__ xq2,
                   const float* __restrict__ xscq,
                   const uint32_t* __restrict__ xh1, const uint32_t* __restrict__ xh2,
                   const float* __restrict__ xsch,
                   const uint32_t* __restrict__ w1, const uint32_t* __restrict__ w2,
                   const float* __restrict__ wsc,
                   const float* __restrict__ qby, const float* __restrict__ qbg,
                   const float* __restrict__ hby, const float* __restrict__ hbg,
                   float* __restrict__ qout, float* __restrict__ hout) {
    extern __shared__ char smem[];
    const uint32_t smem_base = (uint32_t)__cvta_generic_to_shared(smem);
    const int tid  = threadIdx.x;
    const int warp = tid >> 5;
    const int lane = tid & 31;
    const int n0 = blockIdx.x * TBN;

    const bool isq = (blockIdx.y < 5);
    const int m0 = isq ? blockIdx.y * TBM : (blockIdx.y - 5) * TBM;
    const uint32_t* X1 = isq ? xq1 : xh1;
    const uint32_t* X2 = isq ? xq2 : xh2;
    const float* scA = isq ? xscq : xsch;
    const int yrow = (isq ? 0 : 2) * LSTM;
    const int grow = (isq ? 1 : 3) * LSTM;
    const uint32_t* Wy1 = w1 + (size_t)yrow * KW8;
    const uint32_t* Wy2 = w2 + (size_t)yrow * KW8;
    const uint32_t* Wg1 = w1 + (size_t)grow * KW8;
    const uint32_t* Wg2 = w2 + (size_t)grow * KW8;
    const float* scY = wsc + yrow;
    const float* scG = wsc + grow;
    const float* by = isq ? qby : hby;
    const float* bg = isq ? qbg : hbg;
    float* out = isq ? qout : hout;

    // chunk = A1,A2 (128 rows x 128B) + Y1,Y2,G1,G2 (64 rows x 128B), SW128
    auto load_chunk = [&](int c) {
        const uint32_t bb = smem_base + SM_CTRL + (uint32_t)(c & 1) * CH2_BYTES;
        const int kwc = c * 32;
#pragma unroll
        for (int i = 0; i < 8; i++) {
            const uint32_t* basep; int rb, idx; uint32_t doff;
            if (i < 2)      { basep = X1;  rb = m0; doff = 0;     idx = tid + i * 512; }
            else if (i < 4) { basep = X2;  rb = m0; doff = 16384; idx = tid + (i - 2) * 512; }
            else if (i == 4){ basep = Wy1; rb = n0; doff = 32768; idx = tid; }
            else if (i == 5){ basep = Wy2; rb = n0; doff = 40960; idx = tid; }
            else if (i == 6){ basep = Wg1; rb = n0; doff = 49152; idx = tid; }
            else            { basep = Wg2; rb = n0; doff = 57344; idx = tid; }
            const int row = idx >> 3, seg = idx & 7;
            const void* src = basep + (size_t)(rb + row) * KW8 + kwc + seg * 4;
            uint32_t bo = (uint32_t)(row * 128 + seg * 16);
            cpasync16(bb + doff + (bo ^ ((bo >> 3) & 0x70)), src);
        }
        asm volatile("cp.async.commit_group;" ::: "memory");
    };

    const int wm = (warp >> 2) * 32;       // 0,32,64,96
    const int wn = (warp & 3) * 16;        // 0,16,32,48
    int rowA[2], swzA[2];
#pragma unroll
    for (int mt = 0; mt < 2; mt++) {
        rowA[mt] = wm + 16 * mt + (lane & 15);
        swzA[mt] = rowA[mt] & 7;
    }
    const int kselA = lane >> 4;
    const int rowB = wn + (lane & 7) + ((lane & 16) >> 1);
    const int swzB = rowB & 7;
    const int kselB = (lane >> 3) & 1;

    int accYH[2][2][4] = {}, accYM[2][2][4] = {};
    int accGH[2][2][4] = {}, accGM[2][2][4] = {};

    load_chunk(0);
    for (int c = 0; c < NCH2; c++) {
        if (c + 1 < NCH2) {
            load_chunk(c + 1);
            asm volatile("cp.async.wait_group 1;" ::: "memory");
        } else {
            asm volatile("cp.async.wait_group 0;" ::: "memory");
        }
        __syncthreads();
        const uint32_t bb = smem_base + SM_CTRL + (uint32_t)(c & 1) * CH2_BYTES;

#pragma unroll
        for (int ks = 0; ks < 4; ks++) {
            const uint32_t gA = (uint32_t)(2 * ks + kselA);
            const uint32_t gB = (uint32_t)(2 * ks + kselB);

            uint32_t a1f[2][4], a2f[2][4];
#pragma unroll
            for (int mt = 0; mt < 2; mt++) {
                uint32_t off = (uint32_t)(rowA[mt] * 128) + ((gA ^ (uint32_t)swzA[mt]) << 4);
                ldsm_x4(a1f[mt][0], a1f[mt][1], a1f[mt][2], a1f[mt][3], bb + off);
                ldsm_x4(a2f[mt][0], a2f[mt][1], a2f[mt][2], a2f[mt][3], bb + 16384 + off);
            }
            const uint32_t offB = (uint32_t)(rowB * 128) + ((gB ^ (uint32_t)swzB) << 4);

            {
                uint32_t y1[2][2], y2[2][2];
                ldsm_x4(y1[0][0], y1[0][1], y1[1][0], y1[1][1], bb + 32768 + offB);
                ldsm_x4(y2[0][0], y2[0][1], y2[1][0], y2[1][1], bb + 40960 + offB);
#pragma unroll
                for (int nt = 0; nt < 2; nt++)
#pragma unroll
                    for (int mt = 0; mt < 2; mt++) {
                        imma32(accYH[mt][nt], a1f[mt], y1[nt][0], y1[nt][1]);
                        imma32(accYM[mt][nt], a1f[mt], y2[nt][0], y2[nt][1]);
                        imma32(accYM[mt][nt], a2f[mt], y1[nt][0], y1[nt][1]);
                    }
            }
            {
                uint32_t gg1[2][2], gg2[2][2];
                ldsm_x4(gg1[0][0], gg1[0][1], gg1[1][0], gg1[1][1], bb + 49152 + offB);
                ldsm_x4(gg2[0][0], gg2[0][1], gg2[1][0], gg2[1][1], bb + 57344 + offB);
#pragma unroll
                for (int nt = 0; nt < 2; nt++)
#pragma unroll
                    for (int mt = 0; mt < 2; mt++) {
                        imma32(accGH[mt][nt], a1f[mt], gg1[nt][0], gg1[nt][1]);
                        imma32(accGM[mt][nt], a1f[mt], gg2[nt][0], gg2[nt][1]);
                        imma32(accGM[mt][nt], a2f[mt], gg1[nt][0], gg1[nt][1]);
                    }
            }
        }
        __syncthreads();
    }

    const int ar = lane >> 2;
    const int ac = lane & 3;
    const float INV128 = 0.0078125f;
#pragma unroll
    for (int mt = 0; mt < 2; mt++) {
        int gr = m0 + wm + 16 * mt + ar;
        float sA0 = scA[gr], sA1 = scA[gr + 8];
#pragma unroll
        for (int nt = 0; nt < 2; nt++) {
            int gc = n0 + wn + 8 * nt + 2 * ac;
            float sy0 = scY[gc], sy1 = scY[gc + 1];
            float sg0 = scG[gc], sg1 = scG[gc + 1];
            float b_y0 = by[gc], b_y1 = by[gc + 1];
            float b_g0 = bg[gc], b_g1 = bg[gc + 1];

            float y00 = sA0 * sy0 * ((float)accYH[mt][nt][0] + (float)accYM[mt][nt][0] * INV128);
            float y01 = sA0 * sy1 * ((float)accYH[mt][nt][1] + (float)accYM[mt][nt][1] * INV128);
            float y10 = sA1 * sy0 * ((float)accYH[mt][nt][2] + (float)accYM[mt][nt][2] * INV128);
            float y11 = sA1 * sy1 * ((float)accYH[mt][nt][3] + (float)accYM[mt][nt][3] * INV128);
            float g00 = sA0 * sg0 * ((float)accGH[mt][nt][0] + (float)accGM[mt][nt][0] * INV128);
            float g01 = sA0 * sg1 * ((float)accGH[mt][nt][1] + (float)accGM[mt][nt][1] * INV128);
            float g10 = sA1 * sg0 * ((float)accGH[mt][nt][2] + (float)accGM[mt][nt][2] * INV128);
            float g11 = sA1 * sg1 * ((float)accGH[mt][nt][3] + (float)accGM[mt][nt][3] * INV128);

            float v00 = tanhf(y00 + b_y0) * leaky(g00 + b_g0);
            float v01 = tanhf(y01 + b_y1) * leaky(g01 + b_g1);
            float v10 = tanhf(y10 + b_y0) * leaky(g10 + b_g0);
            float v11 = tanhf(y11 + b_y1) * leaky(g11 + b_g1);

            *(float2*)&out[(size_t)gr * LSTM + gc]       = make_float2(v00, v01);
            *(float2*)&out[(size_t)(gr + 8) * LSTM + gc] = make_float2(v10, v11);
        }
    }
}

// ---------------------------------------------------------------------------
// Kernel 2 v2: per-(b,r) attention. cp.async double-buffered score phase,
// register accumulators across all K; float4 topic phase.
// smem floats: emb[12000] | S[800] | buf0[60*132] | buf1[60*132]
// ---------------------------------------------------------------------------
#define A2_S    12000
#define A2_BUF  12800
#define A2_BUFW (60 * 132)                  // 7920 floats per buffer
#define A2_FLOATS (A2_BUF + 2 * A2_BUFW)    // 28640 -> 114560 B

__global__ __launch_bounds__(256)
void attn_v2(const float* __restrict__ qf, const float* __restrict__ hf,
             const float* __restrict__ emb, const float* __restrict__ notpad,
             const float* __restrict__ cms, float* __restrict__ topic) {
    extern __shared__ float sm[];
    const uint32_t smem_base = (uint32_t)__cvta_generic_to_shared(sm);
    const int t = threadIdx.x;
    const int r = blockIdx.x;
    const int b = blockIdx.y;
    const int br = b * NUM_R + r;

    // score-chunk loader: q 20x128 + h 40x128 floats, rows padded to 132
    auto load_chunk = [&](int c) {
        const uint32_t bb = smem_base + (A2_BUF + (c & 1) * A2_BUFW) * 4;
        const int kc = c * 128;
#pragma unroll
        for (int i = 0; i < 8; i++) {
            int idx = t + i * 256;
            if (idx < 640) {
                int row = idx >> 5, seg = idx & 31;
                cpasync16(bb + (uint32_t)(row * 528 + seg * 16),
                          qf + (size_t)(b * SL_Q + row) * LSTM + kc + seg * 4);
            } else if (idx < 1920) {
                int j = idx - 640;
                int row = j >> 5, seg = j & 31;
                cpasync16(bb + (uint32_t)((20 + row) * 528 + seg * 16),
                          hf + (size_t)(br * SL_H + row) * LSTM + kc + seg * 4);
            }
        }
        asm volatile("cp.async.commit_group;" ::: "memory");
    };

    // emb loads ride in chunk-0's async group
    {
        const float* esrc = emb + (size_t)br * (SL_H * WE);
        for (int i = t; i < 3000; i += 256)
            cpasync16(smem_base + (uint32_t)(i * 16), esrc + i * 4);
    }
    load_chunk(0);

    const int q2 = t / 20;   // 0..9 (t<200)
    const int h2 = t % 20;
    float acc00 = 0.f, acc01 = 0.f, acc10 = 0.f, acc11 = 0.f;

    for (int c = 0; c < 8; c++) {
        if (c + 1 < 8) {
            load_chunk(c + 1);
            asm volatile("cp.async.wait_group 1;" ::: "memory");
        } else {
            asm volatile("cp.async.wait_group 0;" ::: "memory");
        }
        __syncthreads();
        if (t < 200) {
            const float* base = sm + A2_BUF + (c & 1) * A2_BUFW;
            const float4* q0p = (const float4*)(base + (2 * q2) * 132);
            const float4* q1p = (const float4*)(base + (2 * q2 + 1) * 132);
            const float4* h0p = (const float4*)(base + (20 + 2 * h2) * 132);
            const float4* h1p = (const float4*)(base + (20 + 2 * h2 + 1) * 132);
#pragma unroll 8
            for (int k = 0; k < 32; k++) {
                float4 q0 = q0p[k], q1 = q1p[k];
                float4 h0 = h0p[k], h1 = h1p[k];
                acc00 += q0.x * h0.x + q0.y * h0.y + q0.z * h0.z + q0.w * h0.w;
                acc01 += q0.x * h1.x + q0.y * h1.y + q0.z * h1.z + q0.w * h1.w;
                acc10 += q1.x * h0.x + q1.y * h0.y + q1.z * h0.z + q1.w * h0.w;
                acc11 += q1.x * h1.x + q1.y * h1.y + q1.z * h1.z + q1.w * h1.w;
            }
        }
        __syncthreads();
    }

    float* S = sm + A2_S;
    if (t < 200) {
        S[(2 * q2)     * SL_H + 2 * h2]     = acc00;
        S[(2 * q2)     * SL_H + 2 * h2 + 1] = acc01;
        S[(2 * q2 + 1) * SL_H + 2 * h2]     = acc10;
        S[(2 * q2 + 1) * SL_H + 2 * h2 + 1] = acc11;
    }
    __syncthreads();

    if (t < SL_Q) {
        float mx = -1e30f;
        for (int h = 0; h < SL_H; h++) {
            float m = notpad[(size_t)br * SL_H + h];
            float s = S[t * SL_H + h] * m + (m - 1.0f) * 10000.0f;
            S[t * SL_H + h] = s;
            mx = fmaxf(mx, s);
        }
        float den = 0.f;
        for (int h = 0; h < SL_H; h++) {
            float e = expf(S[t * SL_H + h] - mx);
            S[t * SL_H + h] = e;
            den += e;
        }
        float inv = 1.0f / den;
        for (int h = 0; h < SL_H; h++) S[t * SL_H + h] *= inv;
    }
    __syncthreads();

    // topic: 20q x 75 float4-groups = 1500 tasks
    const float cmsv = cms[br];
    for (int task = t; task < SL_Q * 75; task += 256) {
        int q = task / 75, eg = task % 75;
        const float* ss = S + q * SL_H;
        float ax = 0.f, ay = 0.f, az = 0.f, aw = 0.f;
#pragma unroll 8
        for (int h = 0; h < SL_H; h++) {
            float a = ss[h];
            float4 e4 = *(const float4*)(sm + h * WE + eg * 4);
            ax += a * e4.x; ay += a * e4.y; az += a * e4.z; aw += a * e4.w;
        }
        float4 o = make_float4(ax * cmsv, ay * cmsv, az * cmsv, aw * cmsv);
        *(float4*)&topic[(size_t)(br * SL_Q + q) * WE + eg * 4] = o;
    }
}

// ---------------------------------------------------------------------------
// Kernel 3: feat = concat(q_embed, sum_r topic)
// ---------------------------------------------------------------------------
__global__ __launch_bounds__(256)
void feat_build(const float* __restrict__ q_embed, const float* __restrict__ topic,
                float* __restrict__ feat) {
    int idx = blockIdx.x * 256 + threadIdx.x;
    int m  = idx / FEATD;
    int e2 = idx % FEATD;
    float v;
    if (e2 < WE) {
        v = q_embed[(size_t)m * WE + e2];
    } else {
        int e = e2 - WE;
        int b = m / SL_Q, q = m % SL_Q;
        v = 0.f;
#pragma unroll
        for (int r = 0; r < NUM_R; r++)
            v += topic[(size_t)((b * NUM_R + r) * SL_Q + q) * WE + e];
    }
    feat[idx] = v;
}

// ---------------------------------------------------------------------------
// Kernel 4: out = sigmoid(feat@Wg + bg) * feat
// ---------------------------------------------------------------------------
#define FBM 64
#define FBN 64
#define FBK 16

__global__ __launch_bounds__(256)
void final_gemm(const float* __restrict__ feat, const float* __restrict__ Wg,
                const float* __restrict__ bg, float* __restrict__ out) {
    __shared__ float Fs[FBM][FBK + 1];
    __shared__ float Bsm[FBK][FBN + 1];

    const int t = threadIdx.x;
    const int ty = t >> 4, tx = t & 15;
    const int m0 = blockIdx.x * FBM;
    const int n0 = blockIdx.y * FBN;

    float acc[4][4];
#pragma unroll
    for (int i = 0; i < 4; i++)
#pragma unroll
        for (int j = 0; j < 4; j++) acc[i][j] = 0.f;

    for (int k0 = 0; k0 < FEATD; k0 += FBK) {
        for (int i = t; i < FBM * FBK; i += 256) {
            int r = i >> 4, c = i & 15;
            int k = k0 + c;
            Fs[r][c] = (k < FEATD) ? feat[(size_t)(m0 + r) * FEATD + k] : 0.f;
        }
        for (int i = t; i < FBK * FBN; i += 256) {
            int r = i >> 6, c = i & 63;
            int k = k0 + r, n = n0 + c;
            Bsm[r][c] = (k < FEATD && n < FEATD) ? Wg[(size_t)k * FEATD + n] : 0.f;
        }
        __syncthreads();
#pragma unroll
        for (int k = 0; k < FBK; k++) {
            float a[4], bb[4];
#pragma unroll
            for (int i = 0; i < 4; i++) a[i]  = Fs[ty * 4 + i][k];
#pragma unroll
            for (int j = 0; j < 4; j++) bb[j] = Bsm[k][tx * 4 + j];
#pragma unroll
            for (int i = 0; i < 4; i++)
#pragma unroll
                for (int j = 0; j < 4; j++) acc[i][j] += a[i] * bb[j];
        }
        __syncthreads();
    }

#pragma unroll
    for (int i = 0; i < 4; i++) {
        int row = m0 + ty * 4 + i;
#pragma unroll
        for (int j = 0; j < 4; j++) {
            int col = n0 + tx * 4 + j;
            if (col < FEATD) {
                float v = acc[i][j] + bg[col];
                float g = 1.0f / (1.0f + expf(-v));
                out[(size_t)row * FEATD + col] = g * feat[(size_t)row * FEATD + col];
            }
        }
    }
}

// ---------------------------------------------------------------------------
// Host launcher
// ---------------------------------------------------------------------------
extern "C" void kernel_launch(void* const* d_in, const int* in_sizes, int n_in,
                              void* d_out, int out_size) {
    const float* q_embed = (const float*)d_in[0];
    const float* q_enc   = (const float*)d_in[1];
    const float* h_embed = (const float*)d_in[2];
    const float* h_enc   = (const float*)d_in[3];
    const float* notpad  = (const float*)d_in[4];
    const float* cms     = (const float*)d_in[5];
    const float* Wq_y = (const float*)d_in[6];
    const float* bq_y = (const float*)d_in[7];
    const float* Wq_g = (const float*)d_in[8];
    const float* bq_g = (const float*)d_in[9];
    const float* Wh_y = (const float*)d_in[10];
    const float* bh_y = (const float*)d_in[11];
    const float* Wh_g = (const float*)d_in[12];
    const float* bh_g = (const float*)d_in[13];
    const float* Wg   = (const float*)d_in[14];
    const float* bg   = (const float*)d_in[15];
    float* out = (float*)d_out;

    float *qf, *hf, *topic, *feat, *wt;
    cudaGetSymbolAddress((void**)&qf,    g_qfeat);
    cudaGetSymbolAddress((void**)&hf,    g_hfeat);
    cudaGetSymbolAddress((void**)&topic, g_topic);
    cudaGetSymbolAddress((void**)&feat,  g_feat);
    cudaGetSymbolAddress((void**)&wt,    g_wt);

    uint32_t *xq1, *xq2, *xh1, *xh2, *w1, *w2;
    float *xscq, *xsch, *wsc;
    cudaGetSymbolAddress((void**)&xq1, g_xq1);
    cudaGetSymbolAddress((void**)&xq2, g_xq2);
    cudaGetSymbolAddress((void**)&xh1, g_xh1);
    cudaGetSymbolAddress((void**)&xh2, g_xh2);
    cudaGetSymbolAddress((void**)&w1,  g_w1);
    cudaGetSymbolAddress((void**)&w2,  g_w2);
    cudaGetSymbolAddress((void**)&xscq, g_xsc_q);
    cudaGetSymbolAddress((void**)&xsch, g_xsc_h);
    cudaGetSymbolAddress((void**)&wsc,  g_wsc);

    cudaFuncSetAttribute(gated_gemm_i8, cudaFuncAttributeMaxDynamicSharedMemorySize,
                         GG2_SMEM);
    cudaFuncSetAttribute(attn_v2, cudaFuncAttributeMaxDynamicSharedMemorySize,
                         A2_FLOATS * (int)sizeof(float));

    // 0: transpose weights (Wq_y, Wq_g, Wh_y, Wh_g)
    wt_transpose<<<dim3(BILSTM / 32, LSTM / 32, 4), 256>>>(Wq_y, Wq_g, Wh_y, Wh_g, wt);

    // 1: fused row quantization (Xq, Xh, Wt)
    quant_rows<<<MQ + MH + NWROWS, 256>>>(q_enc, xq1, xq2, xscq,
                                          h_enc, xh1, xh2, xsch,
                                          wt, w1, w2, wsc);

    // 2: merged gated transforms (int8 imma, 512 threads)
    gated_gemm_i8<<<dim3(LSTM / TBN, 5 + MH / TBM), 512, GG2_SMEM>>>(
        xq1, xq2, xscq, xh1, xh2, xsch, w1, w2, wsc,
        bq_y, bq_g, bh_y, bh_g, qf, hf);

    // 3: attention + topic (v2)
    attn_v2<<<dim3(NUM_R, BS), 256, A2_FLOATS * (int)sizeof(float)>>>(
        qf, hf, h_embed, notpad, cms, topic);

    // 4: concat + reduce over r
    feat_build<<<(MQ * FEATD) / 256, 256>>>(q_embed, topic, feat);

    // 5: final gated output
    final_gemm<<<dim3(MQ / FBM, (FEATD + FBN - 1) / FBN), 256>>>(feat, Wg, bg, out);
}

// round 11
// speedup vs baseline: 1.9612x; 1.9245x over previous
#include <cuda_runtime.h>
#include <cuda_bf16.h>
#include <cstdint>

// ---------------------------------------------------------------------------
// Shapes
// ---------------------------------------------------------------------------
#define BS      32
#define NUM_R   10
#define SL_Q    20
#define SL_H    40
#define WE      300
#define LSTM    1024
#define BILSTM  2048
#define FEATD   600

#define MQ (BS * SL_Q)          // 640
#define MH (BS * NUM_R * SL_H)  // 12800
#define KW (BILSTM / 2)         // 1024 packed bf16x2 words per row

// ---------------------------------------------------------------------------
// Scratch (device globals)
// ---------------------------------------------------------------------------
__device__ float g_qfeat[MQ * LSTM];
__device__ float g_hfeat[MH * LSTM];
__device__ float g_topic[BS * NUM_R * SL_Q * WE];
__device__ float g_feat [MQ * FEATD];

// packed bf16 kpair words (hi / lo split)
__device__ uint32_t g_xq_h[MQ * KW],  g_xq_l[MQ * KW];
__device__ uint32_t g_xh_h[MH * KW],  g_xh_l[MH * KW];
// weights transposed to [N][K] packed: [1024][KW]
__device__ uint32_t g_wqy_h[LSTM * KW], g_wqy_l[LSTM * KW];
__device__ uint32_t g_wqg_h[LSTM * KW], g_wqg_l[LSTM * KW];
__device__ uint32_t g_why_h[LSTM * KW], g_why_l[LSTM * KW];
__device__ uint32_t g_whg_h[LSTM * KW], g_whg_l[LSTM * KW];

// ---------------------------------------------------------------------------
// Helpers
// ---------------------------------------------------------------------------
__device__ __forceinline__ float leaky(float x) {
    return x >= 0.f ? x : 0.01f * x;
}

__device__ __forceinline__ void split2(float a, float b, uint32_t& hi, uint32_t& lo) {
    __nv_bfloat16 ha = __float2bfloat16(a);
    __nv_bfloat16 hb = __float2bfloat16(b);
    __nv_bfloat16 la = __float2bfloat16(a - __bfloat162float(ha));
    __nv_bfloat16 lb = __float2bfloat16(b - __bfloat162float(hb));
    union { __nv_bfloat162 v; uint32_t u; } ph, pl;
    ph.v.x = ha; ph.v.y = hb; pl.v.x = la; pl.v.y = lb;
    hi = ph.u; lo = pl.u;
}

__device__ __forceinline__ void cpasync16(uint32_t dst, const void* src) {
    asm volatile("cp.async.cg.shared.global [%0], [%1], 16;"
                 :: "r"(dst), "l"(src) : "memory");
}

__device__ __forceinline__ void mma_bf16(float c[4], const uint32_t a[4],
                                         uint32_t b0, uint32_t b1) {
    asm volatile(
        "mma.sync.aligned.m16n8k16.row.col.f32.bf16.bf16.f32 "
        "{%0,%1,%2,%3},{%4,%5,%6,%7},{%8,%9},{%0,%1,%2,%3};"
        : "+f"(c[0]), "+f"(c[1]), "+f"(c[2]), "+f"(c[3])
        : "r"(a[0]), "r"(a[1]), "r"(a[2]), "r"(a[3]), "r"(b0), "r"(b1));
}

__device__ __forceinline__ void ldsm_x4(uint32_t& r0, uint32_t& r1,
                                        uint32_t& r2, uint32_t& r3, uint32_t addr) {
    asm volatile("ldmatrix.sync.aligned.m8n8.x4.shared.b16 {%0,%1,%2,%3}, [%4];"
                 : "=r"(r0), "=r"(r1), "=r"(r2), "=r"(r3) : "r"(addr));
}

// ---------------------------------------------------------------------------
// Precompute: X -> packed kpair bf16 hi/lo (proven R7/R8)
// ---------------------------------------------------------------------------
__global__ __launch_bounds__(256)
void split_x_all(const float* __restrict__ xq, uint32_t* __restrict__ qhi,
                 uint32_t* __restrict__ qlo,
                 const float* __restrict__ xh, uint32_t* __restrict__ hhi,
                 uint32_t* __restrict__ hlo) {
    const int n4q = MQ * BILSTM / 4;
    const int n4h = MH * BILSTM / 4;
    int i = blockIdx.x * 256 + threadIdx.x;
    const float* x; uint32_t *hi, *lo; int j;
    if (i < n4q) { x = xq; hi = qhi; lo = qlo; j = i; }
    else if (i < n4q + n4h) { x = xh; hi = hhi; lo = hlo; j = i - n4q; }
    else return;
    float4 v = ((const float4*)x)[j];
    uint32_t h0, l0, h1, l1;
    split2(v.x, v.y, h0, l0);
    split2(v.z, v.w, h1, l1);
    ((uint2*)hi)[j] = make_uint2(h0, h1);
    ((uint2*)lo)[j] = make_uint2(l0, l1);
}

// ---------------------------------------------------------------------------
// Precompute: 4 weight matrices -> transposed packed [1024][KW] hi/lo (proven)
// ---------------------------------------------------------------------------
__global__ __launch_bounds__(256)
void split_wt_all(const float* __restrict__ W0, uint32_t* __restrict__ h0p, uint32_t* __restrict__ l0p,
                  const float* __restrict__ W1, uint32_t* __restrict__ h1p, uint32_t* __restrict__ l1p,
                  const float* __restrict__ W2, uint32_t* __restrict__ h2p, uint32_t* __restrict__ l2p,
                  const float* __restrict__ W3, uint32_t* __restrict__ h3p, uint32_t* __restrict__ l3p) {
    const float* W; uint32_t *thi, *tlo;
    switch (blockIdx.z) {
        case 0:  W = W0; thi = h0p; tlo = l0p; break;
        case 1:  W = W1; thi = h1p; tlo = l1p; break;
        case 2:  W = W2; thi = h2p; tlo = l2p; break;
        default: W = W3; thi = h3p; tlo = l3p; break;
    }
    __shared__ float t[32][33];
    int k0 = blockIdx.x * 32, n0 = blockIdx.y * 32;
    int tx = threadIdx.x & 31, ty = threadIdx.x >> 5;
#pragma unroll
    for (int j = 0; j < 4; j++)
        t[ty + 8 * j][tx] = W[(size_t)(k0 + ty + 8 * j) * LSTM + n0 + tx];
    __syncthreads();
    for (int w = threadIdx.x; w < 512; w += 256) {
        int nn = w >> 4;
        int kp = w & 15;
        uint32_t h, l;
        split2(t[2 * kp][nn], t[2 * kp + 1][nn], h, l);
        size_t o = (size_t)(n0 + nn) * KW + (k0 >> 1) + kp;
        thi[o] = h;
        tlo[o] = l;
    }
}

// ---------------------------------------------------------------------------
// Gated transform: out = tanh(X@Wy+by) * leaky_relu(X@Wg+bg), 3xBF16 HMMA.
// Occupancy-2 tiling: TBM=128, TBN=64, K-chunk 32; 512 thr / 16 warps (4m x 4n);
// warp tile 32x16 (mt=2, nt=2); accs = 64 fp32.
// smem rows: 64B data + 16B pad (80B, stride 20 words) -> ldmatrix conflict-free
// without swizzle. Stage = 6 regions (Ah, Al, Yh, Yl, Gh, Gl) = 40960 B;
// double-buffered + ctrl = 82944 B -> 2 CTAs/SM.
// Grid (16 n-tiles FAST, 105 m-tiles: 0-4 = q, 5-104 = h).
// ---------------------------------------------------------------------------
#define TBM 128
#define TBN 64
#define NCH 64                    // K chunks of 32
#define ROWB 80                   // bytes per smem row
#define RG_A 10240                // 128 rows * 80
#define RG_B 5120                 // 64 rows * 80
#define STAGE (2 * RG_A + 4 * RG_B)   // 40960
#define SM_CTRL 1024
#define GG3_SMEM (SM_CTRL + 2 * STAGE)  // 82944

__global__ __launch_bounds__(512, 2)
void gated_gemm_v3(const uint32_t* __restrict__ qXh, const uint32_t* __restrict__ qXl,
                   const uint32_t* __restrict__ qWyh, const uint32_t* __restrict__ qWyl,
                   const uint32_t* __restrict__ qWgh, const uint32_t* __restrict__ qWgl,
                   const float* __restrict__ qby, const float* __restrict__ qbg,
                   float* __restrict__ qout,
                   const uint32_t* __restrict__ hXh, const uint32_t* __restrict__ hXl,
                   const uint32_t* __restrict__ hWyh, const uint32_t* __restrict__ hWyl,
                   const uint32_t* __restrict__ hWgh, const uint32_t* __restrict__ hWgl,
                   const float* __restrict__ hby, const float* __restrict__ hbg,
                   float* __restrict__ hout) {
    extern __shared__ char smem[];
    const uint32_t smem_base = (uint32_t)__cvta_generic_to_shared(smem);
    const int tid  = threadIdx.x;
    const int warp = tid >> 5;
    const int lane = tid & 31;
    const int n0 = blockIdx.x * TBN;

    const bool isq = (blockIdx.y < 5);
    const int m0 = isq ? blockIdx.y * TBM : (blockIdx.y - 5) * TBM;
    const uint32_t* Xh  = isq ? qXh  : hXh;
    const uint32_t* Xl  = isq ? qXl  : hXl;
    const uint32_t* Wyh = isq ? qWyh : hWyh;
    const uint32_t* Wyl = isq ? qWyl : hWyl;
    const uint32_t* Wgh = isq ? qWgh : hWgh;
    const uint32_t* Wgl = isq ? qWgl : hWgl;
    const float* by = isq ? qby : hby;
    const float* bg = isq ? qbg : hbg;
    float* out = isq ? qout : hout;

    // chunk loader: 2048 cp.async over 512 threads (4 iters)
    // region rows: 64B data per row (4 segs x 16B), stride 80B
    auto load_chunk = [&](int c) {
        const uint32_t bb = smem_base + SM_CTRL + (uint32_t)(c & 1) * STAGE;
        const int kw0 = c * 16;    // 16 words = 32 k-elements per chunk
        {   // i=0: A hi, rows 0..127 (512 entries)
            int row = tid >> 2, seg = tid & 3;
            cpasync16(bb + (uint32_t)(row * ROWB + seg * 16),
                      Xh + (size_t)(m0 + row) * KW + kw0 + seg * 4);
        }
        {   // i=1: A lo
            int row = tid >> 2, seg = tid & 3;
            cpasync16(bb + RG_A + (uint32_t)(row * ROWB + seg * 16),
                      Xl + (size_t)(m0 + row) * KW + kw0 + seg * 4);
        }
        {   // i=2: Y hi (tid<256) / Y lo (tid>=256)
            int j = tid & 255;
            int row = j >> 2, seg = j & 3;
            const uint32_t* s = (tid < 256) ? Wyh : Wyl;
            uint32_t doff = 2 * RG_A + ((tid < 256) ? 0u : (uint32_t)RG_B);
            cpasync16(bb + doff + (uint32_t)(row * ROWB + seg * 16),
                      s + (size_t)(n0 + row) * KW + kw0 + seg * 4);
        }
        {   // i=3: G hi / G lo
            int j = tid & 255;
            int row = j >> 2, seg = j & 3;
            const uint32_t* s = (tid < 256) ? Wgh : Wgl;
            uint32_t doff = 2 * RG_A + 2 * RG_B + ((tid < 256) ? 0u : (uint32_t)RG_B);
            cpasync16(bb + doff + (uint32_t)(row * ROWB + seg * 16),
                      s + (size_t)(n0 + row) * KW + kw0 + seg * 4);
        }
        asm volatile("cp.async.commit_group;" ::: "memory");
    };

    // warp/lane geometry: 16 warps = 4m x 4n; warp tile 32 x 16
    const int wm = (warp >> 2) * 32;       // 0,32,64,96
    const int wn = (warp & 3) * 16;        // 0,16,32,48
    int rowA[2];
#pragma unroll
    for (int mt = 0; mt < 2; mt++) rowA[mt] = wm + 16 * mt + (lane & 15);
    const int kselA = lane >> 4;
    const int rowB = wn + (lane & 7) + ((lane & 16) >> 1);
    const int kselB = (lane >> 3) & 1;

    float accY[2][2][4] = {};
    float accG[2][2][4] = {};

    load_chunk(0);
    for (int c = 0; c < NCH; c++) {
        if (c + 1 < NCH) {
            load_chunk(c + 1);
            asm volatile("cp.async.wait_group 1;" ::: "memory");
        } else {
            asm volatile("cp.async.wait_group 0;" ::: "memory");
        }
        __syncthreads();
        const uint32_t bb = smem_base + SM_CTRL + (uint32_t)(c & 1) * STAGE;

#pragma unroll
        for (int ks = 0; ks < 2; ks++) {
            const uint32_t gA = (uint32_t)(2 * ks + kselA);
            const uint32_t gB = (uint32_t)(2 * ks + kselB);

            uint32_t ah[2][4], al[2][4];
#pragma unroll
            for (int mt = 0; mt < 2; mt++) {
                uint32_t off = (uint32_t)(rowA[mt] * ROWB) + gA * 16;
                ldsm_x4(ah[mt][0], ah[mt][1], ah[mt][2], ah[mt][3], bb + off);
                ldsm_x4(al[mt][0], al[mt][1], al[mt][2], al[mt][3], bb + RG_A + off);
            }
            const uint32_t offB = (uint32_t)(rowB * ROWB) + gB * 16;

            {   // Y branch
                uint32_t yh[2][2], yl[2][2];
                ldsm_x4(yh[0][0], yh[0][1], yh[1][0], yh[1][1], bb + 2 * RG_A + offB);
                ldsm_x4(yl[0][0], yl[0][1], yl[1][0], yl[1][1], bb + 2 * RG_A + RG_B + offB);
#pragma unroll
                for (int nt = 0; nt < 2; nt++)
#pragma unroll
                    for (int mt = 0; mt < 2; mt++) {
                        mma_bf16(accY[mt][nt], al[mt], yh[nt][0], yh[nt][1]);
                        mma_bf16(accY[mt][nt], ah[mt], yl[nt][0], yl[nt][1]);
                        mma_bf16(accY[mt][nt], ah[mt], yh[nt][0], yh[nt][1]);
                    }
            }
            {   // G branch
                uint32_t gh[2][2], gl[2][2];
                ldsm_x4(gh[0][0], gh[0][1], gh[1][0], gh[1][1], bb + 2 * RG_A + 2 * RG_B + offB);
                ldsm_x4(gl[0][0], gl[0][1], gl[1][0], gl[1][1], bb + 2 * RG_A + 3 * RG_B + offB);
#pragma unroll
                for (int nt = 0; nt < 2; nt++)
#pragma unroll
                    for (int mt = 0; mt < 2; mt++) {
                        mma_bf16(accG[mt][nt], al[mt], gh[nt][0], gh[nt][1]);
                        mma_bf16(accG[mt][nt], ah[mt], gl[nt][0], gl[nt][1]);
                        mma_bf16(accG[mt][nt], ah[mt], gh[nt][0], gh[nt][1]);
                    }
            }
        }
        __syncthreads();
    }

    // epilogue: bias + tanh * leaky_relu
    const int ar = lane >> 2;
    const int ac = lane & 3;
#pragma unroll
    for (int mt = 0; mt < 2; mt++) {
        int gr = m0 + wm + 16 * mt + ar;
#pragma unroll
        for (int nt = 0; nt < 2; nt++) {
            int gc = n0 + wn + 8 * nt + 2 * ac;
            float b_y0 = by[gc], b_y1 = by[gc + 1];
            float b_g0 = bg[gc], b_g1 = bg[gc + 1];
            float v00 = tanhf(accY[mt][nt][0] + b_y0) * leaky(accG[mt][nt][0] + b_g0);
            float v01 = tanhf(accY[mt][nt][1] + b_y1) * leaky(accG[mt][nt][1] + b_g1);
            float v10 = tanhf(accY[mt][nt][2] + b_y0) * leaky(accG[mt][nt][2] + b_g0);
            float v11 = tanhf(accY[mt][nt][3] + b_y1) * leaky(accG[mt][nt][3] + b_g1);
            *(float2*)&out[(size_t)gr * LSTM + gc]       = make_float2(v00, v01);
            *(float2*)&out[(size_t)(gr + 8) * LSTM + gc] = make_float2(v10, v11);
        }
    }
}

// ---------------------------------------------------------------------------
// Kernel 2: attn_v2 (proven in R10: 74.8 us)
// ---------------------------------------------------------------------------
#define A2_S    12000
#define A2_BUF  12800
#define A2_BUFW (60 * 132)
#define A2_FLOATS (A2_BUF + 2 * A2_BUFW)

__global__ __launch_bounds__(256)
void attn_v2(const float* __restrict__ qf, const float* __restrict__ hf,
             const float* __restrict__ emb, const float* __restrict__ notpad,
             const float* __restrict__ cms, float* __restrict__ topic) {
    extern __shared__ float sm[];
    const uint32_t smem_base = (uint32_t)__cvta_generic_to_shared(sm);
    const int t = threadIdx.x;
    const int r = blockIdx.x;
    const int b = blockIdx.y;
    const int br = b * NUM_R + r;

    auto load_chunk = [&](int c) {
        const uint32_t bb = smem_base + (A2_BUF + (c & 1) * A2_BUFW) * 4;
        const int kc = c * 128;
#pragma unroll
        for (int i = 0; i < 8; i++) {
            int idx = t + i * 256;
            if (idx < 640) {
                int row = idx >> 5, seg = idx & 31;
                cpasync16(bb + (uint32_t)(row * 528 + seg * 16),
                          qf + (size_t)(b * SL_Q + row) * LSTM + kc + seg * 4);
            } else if (idx < 1920) {
                int j = idx - 640;
                int row = j >> 5, seg = j & 31;
                cpasync16(bb + (uint32_t)((20 + row) * 528 + seg * 16),
                          hf + (size_t)(br * SL_H + row) * LSTM + kc + seg * 4);
            }
        }
        asm volatile("cp.async.commit_group;" ::: "memory");
    };

    {
        const float* esrc = emb + (size_t)br * (SL_H * WE);
        for (int i = t; i < 3000; i += 256)
            cpasync16(smem_base + (uint32_t)(i * 16), esrc + i * 4);
    }
    load_chunk(0);

    const int q2 = t / 20;
    const int h2 = t % 20;
    float acc00 = 0.f, acc01 = 0.f, acc10 = 0.f, acc11 = 0.f;

    for (int c = 0; c < 8; c++) {
        if (c + 1 < 8) {
            load_chunk(c + 1);
            asm volatile("cp.async.wait_group 1;" ::: "memory");
        } else {
            asm volatile("cp.async.wait_group 0;" ::: "memory");
        }
        __syncthreads();
        if (t < 200) {
            const float* base = sm + A2_BUF + (c & 1) * A2_BUFW;
            const float4* q0p = (const float4*)(base + (2 * q2) * 132);
            const float4* q1p = (const float4*)(base + (2 * q2 + 1) * 132);
            const float4* h0p = (const float4*)(base + (20 + 2 * h2) * 132);
            const float4* h1p = (const float4*)(base + (20 + 2 * h2 + 1) * 132);
#pragma unroll 8
            for (int k = 0; k < 32; k++) {
                float4 q0 = q0p[k], q1 = q1p[k];
                float4 h0 = h0p[k], h1 = h1p[k];
                acc00 += q0.x * h0.x + q0.y * h0.y + q0.z * h0.z + q0.w * h0.w;
                acc01 += q0.x * h1.x + q0.y * h1.y + q0.z * h1.z + q0.w * h1.w;
                acc10 += q1.x * h0.x + q1.y * h0.y + q1.z * h0.z + q1.w * h0.w;
                acc11 += q1.x * h1.x + q1.y * h1.y + q1.z * h1.z + q1.w * h1.w;
            }
        }
        __syncthreads();
    }

    float* S = sm + A2_S;
    if (t < 200) {
        S[(2 * q2)     * SL_H + 2 * h2]     = acc00;
        S[(2 * q2)     * SL_H + 2 * h2 + 1] = acc01;
        S[(2 * q2 + 1) * SL_H + 2 * h2]     = acc10;
        S[(2 * q2 + 1) * SL_H + 2 * h2 + 1] = acc11;
    }
    __syncthreads();

    if (t < SL_Q) {
        float mx = -1e30f;
        for (int h = 0; h < SL_H; h++) {
            float m = notpad[(size_t)br * SL_H + h];
            float s = S[t * SL_H + h] * m + (m - 1.0f) * 10000.0f;
            S[t * SL_H + h] = s;
            mx = fmaxf(mx, s);
        }
        float den = 0.f;
        for (int h = 0; h < SL_H; h++) {
            float e = expf(S[t * SL_H + h] - mx);
            S[t * SL_H + h] = e;
            den += e;
        }
        float inv = 1.0f / den;
        for (int h = 0; h < SL_H; h++) S[t * SL_H + h] *= inv;
    }
    __syncthreads();

    const float cmsv = cms[br];
    for (int task = t; task < SL_Q * 75; task += 256) {
        int q = task / 75, eg = task % 75;
        const float* ss = S + q * SL_H;
        float ax = 0.f, ay = 0.f, az = 0.f, aw = 0.f;
#pragma unroll 8
        for (int h = 0; h < SL_H; h++) {
            float a = ss[h];
            float4 e4 = *(const float4*)(sm + h * WE + eg * 4);
            ax += a * e4.x; ay += a * e4.y; az += a * e4.z; aw += a * e4.w;
        }
        float4 o = make_float4(ax * cmsv, ay * cmsv, az * cmsv, aw * cmsv);
        *(float4*)&topic[(size_t)(br * SL_Q + q) * WE + eg * 4] = o;
    }
}

// ---------------------------------------------------------------------------
// Kernel 3: feat = concat(q_embed, sum_r topic)
// ---------------------------------------------------------------------------
__global__ __launch_bounds__(256)
void feat_build(const float* __restrict__ q_embed, const float* __restrict__ topic,
                float* __restrict__ feat) {
    int idx = blockIdx.x * 256 + threadIdx.x;
    int m  = idx / FEATD;
    int e2 = idx % FEATD;
    float v;
    if (e2 < WE) {
        v = q_embed[(size_t)m * WE + e2];
    } else {
        int e = e2 - WE;
        int b = m / SL_Q, q = m % SL_Q;
        v = 0.f;
#pragma unroll
        for (int r = 0; r < NUM_R; r++)
            v += topic[(size_t)((b * NUM_R + r) * SL_Q + q) * WE + e];
    }
    feat[idx] = v;
}

// ---------------------------------------------------------------------------
// Kernel 4: out = sigmoid(feat@Wg + bg) * feat
// ---------------------------------------------------------------------------
#define FBM 64
#define FBN 64
#define FBK 16

__global__ __launch_bounds__(256)
void final_gemm(const float* __restrict__ feat, const float* __restrict__ Wg,
                const float* __restrict__ bg, float* __restrict__ out) {
    __shared__ float Fs[FBM][FBK + 1];
    __shared__ float Bsm[FBK][FBN + 1];

    const int t = threadIdx.x;
    const int ty = t >> 4, tx = t & 15;
    const int m0 = blockIdx.x * FBM;
    const int n0 = blockIdx.y * FBN;

    float acc[4][4];
#pragma unroll
    for (int i = 0; i < 4; i++)
#pragma unroll
        for (int j = 0; j < 4; j++) acc[i][j] = 0.f;

    for (int k0 = 0; k0 < FEATD; k0 += FBK) {
        for (int i = t; i < FBM * FBK; i += 256) {
            int r = i >> 4, c = i & 15;
            int k = k0 + c;
            Fs[r][c] = (k < FEATD) ? feat[(size_t)(m0 + r) * FEATD + k] : 0.f;
        }
        for (int i = t; i < FBK * FBN; i += 256) {
            int r = i >> 6, c = i & 63;
            int k = k0 + r, n = n0 + c;
            Bsm[r][c] = (k < FEATD && n < FEATD) ? Wg[(size_t)k * FEATD + n] : 0.f;
        }
        __syncthreads();
#pragma unroll
        for (int k = 0; k < FBK; k++) {
            float a[4], bb[4];
#pragma unroll
            for (int i = 0; i < 4; i++) a[i]  = Fs[ty * 4 + i][k];
#pragma unroll
            for (int j = 0; j < 4; j++) bb[j] = Bsm[k][tx * 4 + j];
#pragma unroll
            for (int i = 0; i < 4; i++)
#pragma unroll
                for (int j = 0; j < 4; j++) acc[i][j] += a[i] * bb[j];
        }
        __syncthreads();
    }

#pragma unroll
    for (int i = 0; i < 4; i++) {
        int row = m0 + ty * 4 + i;
#pragma unroll
        for (int j = 0; j < 4; j++) {
            int col = n0 + tx * 4 + j;
            if (col < FEATD) {
                float v = acc[i][j] + bg[col];
                float g = 1.0f / (1.0f + expf(-v));
                out[(size_t)row * FEATD + col] = g * feat[(size_t)row * FEATD + col];
            }
        }
    }
}

// ---------------------------------------------------------------------------
// Host launcher
// ---------------------------------------------------------------------------
extern "C" void kernel_launch(void* const* d_in, const int* in_sizes, int n_in,
                              void* d_out, int out_size) {
    const float* q_embed = (const float*)d_in[0];
    const float* q_enc   = (const float*)d_in[1];
    const float* h_embed = (const float*)d_in[2];
    const float* h_enc   = (const float*)d_in[3];
    const float* notpad  = (const float*)d_in[4];
    const float* cms     = (const float*)d_in[5];
    const float* Wq_y = (const float*)d_in[6];
    const float* bq_y = (const float*)d_in[7];
    const float* Wq_g = (const float*)d_in[8];
    const float* bq_g = (const float*)d_in[9];
    const float* Wh_y = (const float*)d_in[10];
    const float* bh_y = (const float*)d_in[11];
    const float* Wh_g = (const float*)d_in[12];
    const float* bh_g = (const float*)d_in[13];
    const float* Wg   = (const float*)d_in[14];
    const float* bg   = (const float*)d_in[15];
    float* out = (float*)d_out;

    float *qf, *hf, *topic, *feat;
    cudaGetSymbolAddress((void**)&qf,    g_qfeat);
    cudaGetSymbolAddress((void**)&hf,    g_hfeat);
    cudaGetSymbolAddress((void**)&topic, g_topic);
    cudaGetSymbolAddress((void**)&feat,  g_feat);

    uint32_t *xq_h, *xq_l, *xh_h, *xh_l;
    uint32_t *wqy_h, *wqy_l, *wqg_h, *wqg_l, *why_h, *why_l, *whg_h, *whg_l;
    cudaGetSymbolAddress((void**)&xq_h, g_xq_h);
    cudaGetSymbolAddress((void**)&xq_l, g_xq_l);
    cudaGetSymbolAddress((void**)&xh_h, g_xh_h);
    cudaGetSymbolAddress((void**)&xh_l, g_xh_l);
    cudaGetSymbolAddress((void**)&wqy_h, g_wqy_h);
    cudaGetSymbolAddress((void**)&wqy_l, g_wqy_l);
    cudaGetSymbolAddress((void**)&wqg_h, g_wqg_h);
    cudaGetSymbolAddress((void**)&wqg_l, g_wqg_l);
    cudaGetSymbolAddress((void**)&why_h, g_why_h);
    cudaGetSymbolAddress((void**)&why_l, g_why_l);
    cudaGetSymbolAddress((void**)&whg_h, g_whg_h);
    cudaGetSymbolAddress((void**)&whg_l, g_whg_l);

    cudaFuncSetAttribute(gated_gemm_v3, cudaFuncAttributeMaxDynamicSharedMemorySize,
                         GG3_SMEM);
    cudaFuncSetAttribute(attn_v2, cudaFuncAttributeMaxDynamicSharedMemorySize,
                         A2_FLOATS * (int)sizeof(float));

    // 0: fused X splits
    {
        int n4 = (MQ + MH) * BILSTM / 4;
        split_x_all<<<(n4 + 255) / 256, 256>>>(q_enc, xq_h, xq_l, h_enc, xh_h, xh_l);
    }
    // 1: fused transposed W splits
    {
        dim3 wg(BILSTM / 32, LSTM / 32, 4);
        split_wt_all<<<wg, 256>>>(Wq_y, wqy_h, wqy_l, Wq_g, wqg_h, wqg_l,
                                  Wh_y, why_h, why_l, Wh_g, whg_h, whg_l);
    }
    // 2: merged gated transforms (bf16 3x, occupancy-2 tiling)
    gated_gemm_v3<<<dim3(LSTM / TBN, 5 + MH / TBM), 512, GG3_SMEM>>>(
        xq_h, xq_l, wqy_h, wqy_l, wqg_h, wqg_l, bq_y, bq_g, qf,
        xh_h, xh_l, why_h, why_l, whg_h, whg_l, bh_y, bh_g, hf);

    // 3: attention + topic
    attn_v2<<<dim3(NUM_R, BS), 256, A2_FLOATS * (int)sizeof(float)>>>(
        qf, hf, h_embed, notpad, cms, topic);

    // 4: concat + reduce over r
    feat_build<<<(MQ * FEATD) / 256, 256>>>(q_embed, topic, feat);

    // 5: final gated output
    final_gemm<<<dim3(MQ / FBM, (FEATD + FBN - 1) / FBN), 256>>>(feat, Wg, bg, out);
}

// round 12
// speedup vs baseline: 2.7696x; 1.4122x over previous
#include <cuda_runtime.h>
#include <cuda_bf16.h>
#include <cstdint>

// ---------------------------------------------------------------------------
// Shapes
// ---------------------------------------------------------------------------
#define BS      32
#define NUM_R   10
#define SL_Q    20
#define SL_H    40
#define WE      300
#define LSTM    1024
#define BILSTM  2048
#define FEATD   600

#define MQ (BS * SL_Q)          // 640
#define MH (BS * NUM_R * SL_H)  // 12800
#define KW (BILSTM / 2)         // 1024 packed bf16x2 words per row

// ---------------------------------------------------------------------------
// Scratch (device globals)
// ---------------------------------------------------------------------------
__device__ float g_qfeat[MQ * LSTM];
__device__ float g_hfeat[MH * LSTM];
__device__ float g_topic[BS * NUM_R * SL_Q * WE];
__device__ float g_feat [MQ * FEATD];

__device__ uint32_t g_xq_h[MQ * KW],  g_xq_l[MQ * KW];
__device__ uint32_t g_xh_h[MH * KW],  g_xh_l[MH * KW];
__device__ uint32_t g_wqy_h[LSTM * KW], g_wqy_l[LSTM * KW];
__device__ uint32_t g_wqg_h[LSTM * KW], g_wqg_l[LSTM * KW];
__device__ uint32_t g_why_h[LSTM * KW], g_why_l[LSTM * KW];
__device__ uint32_t g_whg_h[LSTM * KW], g_whg_l[LSTM * KW];

// ---------------------------------------------------------------------------
// Helpers
// ---------------------------------------------------------------------------
__device__ __forceinline__ float leaky(float x) {
    return x >= 0.f ? x : 0.01f * x;
}

__device__ __forceinline__ void split2(float a, float b, uint32_t& hi, uint32_t& lo) {
    __nv_bfloat16 ha = __float2bfloat16(a);
    __nv_bfloat16 hb = __float2bfloat16(b);
    __nv_bfloat16 la = __float2bfloat16(a - __bfloat162float(ha));
    __nv_bfloat16 lb = __float2bfloat16(b - __bfloat162float(hb));
    union { __nv_bfloat162 v; uint32_t u; } ph, pl;
    ph.v.x = ha; ph.v.y = hb; pl.v.x = la; pl.v.y = lb;
    hi = ph.u; lo = pl.u;
}

__device__ __forceinline__ void cpasync16(uint32_t dst, const void* src) {
    asm volatile("cp.async.cg.shared.global [%0], [%1], 16;"
                 :: "r"(dst), "l"(src) : "memory");
}

__device__ __forceinline__ void mma_bf16(float c[4], const uint32_t a[4],
                                         uint32_t b0, uint32_t b1) {
    asm volatile(
        "mma.sync.aligned.m16n8k16.row.col.f32.bf16.bf16.f32 "
        "{%0,%1,%2,%3},{%4,%5,%6,%7},{%8,%9},{%0,%1,%2,%3};"
        : "+f"(c[0]), "+f"(c[1]), "+f"(c[2]), "+f"(c[3])
        : "r"(a[0]), "r"(a[1]), "r"(a[2]), "r"(a[3]), "r"(b0), "r"(b1));
}

__device__ __forceinline__ void ldsm_x4(uint32_t& r0, uint32_t& r1,
                                        uint32_t& r2, uint32_t& r3, uint32_t addr) {
    asm volatile("ldmatrix.sync.aligned.m8n8.x4.shared.b16 {%0,%1,%2,%3}, [%4];"
                 : "=r"(r0), "=r"(r1), "=r"(r2), "=r"(r3) : "r"(addr));
}

// ---------------------------------------------------------------------------
// Precompute (fused): X_q and X_h -> packed kpair bf16 hi/lo words (proven R8)
// ---------------------------------------------------------------------------
__global__ __launch_bounds__(256)
void split_x_all(const float* __restrict__ xq, uint32_t* __restrict__ qhi,
                 uint32_t* __restrict__ qlo,
                 const float* __restrict__ xh, uint32_t* __restrict__ hhi,
                 uint32_t* __restrict__ hlo) {
    const int n4q = MQ * BILSTM / 4;
    const int n4h = MH * BILSTM / 4;
    int i = blockIdx.x * 256 + threadIdx.x;
    const float* x; uint32_t *hi, *lo; int j;
    if (i < n4q) { x = xq; hi = qhi; lo = qlo; j = i; }
    else if (i < n4q + n4h) { x = xh; hi = hhi; lo = hlo; j = i - n4q; }
    else return;
    float4 v = ((const float4*)x)[j];
    uint32_t h0, l0, h1, l1;
    split2(v.x, v.y, h0, l0);
    split2(v.z, v.w, h1, l1);
    ((uint2*)hi)[j] = make_uint2(h0, h1);
    ((uint2*)lo)[j] = make_uint2(l0, l1);
}

// ---------------------------------------------------------------------------
// Precompute (fused): 4 weights -> transposed packed [1024][KW] hi/lo (proven)
// ---------------------------------------------------------------------------
__global__ __launch_bounds__(256)
void split_wt_all(const float* __restrict__ W0, uint32_t* __restrict__ h0p, uint32_t* __restrict__ l0p,
                  const float* __restrict__ W1, uint32_t* __restrict__ h1p, uint32_t* __restrict__ l1p,
                  const float* __restrict__ W2, uint32_t* __restrict__ h2p, uint32_t* __restrict__ l2p,
                  const float* __restrict__ W3, uint32_t* __restrict__ h3p, uint32_t* __restrict__ l3p) {
    const float* W; uint32_t *thi, *tlo;
    switch (blockIdx.z) {
        case 0:  W = W0; thi = h0p; tlo = l0p; break;
        case 1:  W = W1; thi = h1p; tlo = l1p; break;
        case 2:  W = W2; thi = h2p; tlo = l2p; break;
        default: W = W3; thi = h3p; tlo = l3p; break;
    }
    __shared__ float t[32][33];
    int k0 = blockIdx.x * 32, n0 = blockIdx.y * 32;
    int tx = threadIdx.x & 31, ty = threadIdx.x >> 5;
#pragma unroll
    for (int j = 0; j < 4; j++)
        t[ty + 8 * j][tx] = W[(size_t)(k0 + ty + 8 * j) * LSTM + n0 + tx];
    __syncthreads();
    for (int w = threadIdx.x; w < 512; w += 256) {
        int nn = w >> 4;
        int kp = w & 15;
        uint32_t h, l;
        split2(t[2 * kp][nn], t[2 * kp + 1][nn], h, l);
        size_t o = (size_t)(n0 + nn) * KW + (k0 >> 1) + kp;
        thi[o] = h;
        tlo[o] = l;
    }
}

// ---------------------------------------------------------------------------
// Gated transform (R8's proven legacy config, verbatim):
// out = tanh(X@Wy+by) * leaky_relu(X@Wg+bg), 3xBF16 m16n8k16 HMMA.
// Merged q+h: grid (8 n-tiles FAST, 105 m-tiles: 0-4=q, 5-104=h).
// Tile 128x128, K-chunk 64, cp.async double-buffered, ldmatrix, SW128 swizzle.
// 8 warps: 2m x 4n, warp tile 64x32; 256 threads, 1 CTA/SM.
// ---------------------------------------------------------------------------
#define TBM 128
#define TBN 128
#define TKC 64
#define NCHUNK (BILSTM / TKC)          // 32
#define CH_BYTES 98304
#define SM_CTRL 1024
#define GG_SMEM (SM_CTRL + 2 * CH_BYTES)

__global__ __launch_bounds__(256, 1)
void gated_gemm_all(const uint32_t* __restrict__ qXh, const uint32_t* __restrict__ qXl,
                    const uint32_t* __restrict__ qWyh, const uint32_t* __restrict__ qWyl,
                    const uint32_t* __restrict__ qWgh, const uint32_t* __restrict__ qWgl,
                    const float* __restrict__ qby, const float* __restrict__ qbg,
                    float* __restrict__ qout,
                    const uint32_t* __restrict__ hXh, const uint32_t* __restrict__ hXl,
                    const uint32_t* __restrict__ hWyh, const uint32_t* __restrict__ hWyl,
                    const uint32_t* __restrict__ hWgh, const uint32_t* __restrict__ hWgl,
                    const float* __restrict__ hby, const float* __restrict__ hbg,
                    float* __restrict__ hout) {
    extern __shared__ char smem[];
    const uint32_t smem_base = (uint32_t)__cvta_generic_to_shared(smem);
    const int tid  = threadIdx.x;
    const int warp = tid >> 5;
    const int lane = tid & 31;
    const int n0 = blockIdx.x * TBN;

    const bool isq = (blockIdx.y < 5);
    const int m0 = isq ? blockIdx.y * TBM : (blockIdx.y - 5) * TBM;
    const uint32_t* Xh  = isq ? qXh  : hXh;
    const uint32_t* Xl  = isq ? qXl  : hXl;
    const uint32_t* Wyh = isq ? qWyh : hWyh;
    const uint32_t* Wyl = isq ? qWyl : hWyl;
    const uint32_t* Wgh = isq ? qWgh : hWgh;
    const uint32_t* Wgl = isq ? qWgl : hWgl;
    const float* by = isq ? qby : hby;
    const float* bg = isq ? qbg : hbg;
    float* out = isq ? qout : hout;

    auto load_chunk = [&](int c) {
        const uint32_t bb = smem_base + SM_CTRL + (uint32_t)(c & 1) * CH_BYTES;
        const int kw0 = c * (TKC / 2);
#pragma unroll
        for (int i = 0; i < 24; i++) {
            const int reg = i >> 2;
            const int v   = tid + (i & 3) * 256;
            const int row = v >> 3, seg = v & 7;
            const uint32_t* s; int rb; uint32_t doff;
            if      (reg == 0) { s = Xh;  rb = m0; doff = 0; }
            else if (reg == 1) { s = Xl;  rb = m0; doff = 16384; }
            else if (reg == 2) { s = Wyh; rb = n0; doff = 32768; }
            else if (reg == 3) { s = Wyl; rb = n0; doff = 49152; }
            else if (reg == 4) { s = Wgh; rb = n0; doff = 65536; }
            else               { s = Wgl; rb = n0; doff = 81920; }
            const void* src = s + (size_t)(rb + row) * KW + kw0 + seg * 4;
            uint32_t bo = (uint32_t)(row * 128 + seg * 16);
            cpasync16(bb + doff + (bo ^ ((bo >> 3) & 0x70)), src);
        }
        asm volatile("cp.async.commit_group;" ::: "memory");
    };

    // 8 warps: 2m x 4n, warp tile 64x32 (mt=4, nt=4)
    const int wm = (warp >> 2) * 64;
    const int wn = (warp & 3) * 32;

    int rowA[4], swzA[4];
#pragma unroll
    for (int mt = 0; mt < 4; mt++) {
        rowA[mt] = wm + 16 * mt + (lane & 15);
        swzA[mt] = rowA[mt] & 7;
    }
    const int kselA = lane >> 4;
    int rowB[2], swzB[2];
#pragma unroll
    for (int ntp = 0; ntp < 2; ntp++) {
        rowB[ntp] = wn + 16 * ntp + (lane & 7) + ((lane & 16) >> 1);
        swzB[ntp] = rowB[ntp] & 7;
    }
    const int kselB = (lane >> 3) & 1;

    float accY[4][4][4] = {};
    float accG[4][4][4] = {};

    load_chunk(0);
    for (int c = 0; c < NCHUNK; c++) {
        if (c + 1 < NCHUNK) {
            load_chunk(c + 1);
            asm volatile("cp.async.wait_group 1;" ::: "memory");
        } else {
            asm volatile("cp.async.wait_group 0;" ::: "memory");
        }
        __syncthreads();
        const uint32_t bb = smem_base + SM_CTRL + (uint32_t)(c & 1) * CH_BYTES;

#pragma unroll
        for (int ks = 0; ks < 4; ks++) {
            const uint32_t gA = (uint32_t)(2 * ks + kselA);
            const uint32_t gB = (uint32_t)(2 * ks + kselB);
            uint32_t ah[4][4], al[4][4];
#pragma unroll
            for (int mt = 0; mt < 4; mt++) {
                uint32_t off = (uint32_t)(rowA[mt] * 128) + ((gA ^ (uint32_t)swzA[mt]) << 4);
                ldsm_x4(ah[mt][0], ah[mt][1], ah[mt][2], ah[mt][3], bb + off);
                ldsm_x4(al[mt][0], al[mt][1], al[mt][2], al[mt][3], bb + 16384 + off);
            }
            uint32_t offB[2];
#pragma unroll
            for (int ntp = 0; ntp < 2; ntp++)
                offB[ntp] = (uint32_t)(rowB[ntp] * 128) + ((gB ^ (uint32_t)swzB[ntp]) << 4);

            {   // Y branch
                uint32_t byh[4][2], byl[4][2];
#pragma unroll
                for (int ntp = 0; ntp < 2; ntp++) {
                    ldsm_x4(byh[2*ntp][0], byh[2*ntp][1], byh[2*ntp+1][0], byh[2*ntp+1][1],
                            bb + 32768 + offB[ntp]);
                    ldsm_x4(byl[2*ntp][0], byl[2*ntp][1], byl[2*ntp+1][0], byl[2*ntp+1][1],
                            bb + 49152 + offB[ntp]);
                }
#pragma unroll
                for (int nt = 0; nt < 4; nt++)
#pragma unroll
                    for (int mt = 0; mt < 4; mt++) {
                        mma_bf16(accY[mt][nt], al[mt], byh[nt][0], byh[nt][1]);
                        mma_bf16(accY[mt][nt], ah[mt], byl[nt][0], byl[nt][1]);
                        mma_bf16(accY[mt][nt], ah[mt], byh[nt][0], byh[nt][1]);
                    }
            }
            {   // G branch
                uint32_t bgh[4][2], bgl[4][2];
#pragma unroll
                for (int ntp = 0; ntp < 2; ntp++) {
                    ldsm_x4(bgh[2*ntp][0], bgh[2*ntp][1], bgh[2*ntp+1][0], bgh[2*ntp+1][1],
                            bb + 65536 + offB[ntp]);
                    ldsm_x4(bgl[2*ntp][0], bgl[2*ntp][1], bgl[2*ntp+1][0], bgl[2*ntp+1][1],
                            bb + 81920 + offB[ntp]);
                }
#pragma unroll
                for (int nt = 0; nt < 4; nt++)
#pragma unroll
                    for (int mt = 0; mt < 4; mt++) {
                        mma_bf16(accG[mt][nt], al[mt], bgh[nt][0], bgh[nt][1]);
                        mma_bf16(accG[mt][nt], ah[mt], bgl[nt][0], bgl[nt][1]);
                        mma_bf16(accG[mt][nt], ah[mt], bgh[nt][0], bgh[nt][1]);
                    }
            }
        }
        __syncthreads();
    }

    const int ar = lane >> 2;
    const int ac = lane & 3;
#pragma unroll
    for (int mt = 0; mt < 4; mt++) {
#pragma unroll
        for (int nt = 0; nt < 4; nt++) {
            int gr = m0 + wm + 16 * mt + ar;
            int gc = n0 + wn + 8 * nt + 2 * ac;
            float b_y0 = by[gc], b_y1 = by[gc + 1];
            float b_g0 = bg[gc], b_g1 = bg[gc + 1];
            float v00 = tanhf(accY[mt][nt][0] + b_y0) * leaky(accG[mt][nt][0] + b_g0);
            float v01 = tanhf(accY[mt][nt][1] + b_y1) * leaky(accG[mt][nt][1] + b_g1);
            float v10 = tanhf(accY[mt][nt][2] + b_y0) * leaky(accG[mt][nt][2] + b_g0);
            float v11 = tanhf(accY[mt][nt][3] + b_y1) * leaky(accG[mt][nt][3] + b_g1);
            *(float2*)&out[(size_t)gr * LSTM + gc]       = make_float2(v00, v01);
            *(float2*)&out[(size_t)(gr + 8) * LSTM + gc] = make_float2(v10, v11);
        }
    }
}

// ---------------------------------------------------------------------------
// Kernel 2: attn_v2 (proven 75 us in R10 and R11)
// ---------------------------------------------------------------------------
#define A2_S    12000
#define A2_BUF  12800
#define A2_BUFW (60 * 132)
#define A2_FLOATS (A2_BUF + 2 * A2_BUFW)

__global__ __launch_bounds__(256)
void attn_v2(const float* __restrict__ qf, const float* __restrict__ hf,
             const float* __restrict__ emb, const float* __restrict__ notpad,
             const float* __restrict__ cms, float* __restrict__ topic) {
    extern __shared__ float sm[];
    const uint32_t smem_base = (uint32_t)__cvta_generic_to_shared(sm);
    const int t = threadIdx.x;
    const int r = blockIdx.x;
    const int b = blockIdx.y;
    const int br = b * NUM_R + r;

    auto load_chunk = [&](int c) {
        const uint32_t bb = smem_base + (A2_BUF + (c & 1) * A2_BUFW) * 4;
        const int kc = c * 128;
#pragma unroll
        for (int i = 0; i < 8; i++) {
            int idx = t + i * 256;
            if (idx < 640) {
                int row = idx >> 5, seg = idx & 31;
                cpasync16(bb + (uint32_t)(row * 528 + seg * 16),
                          qf + (size_t)(b * SL_Q + row) * LSTM + kc + seg * 4);
            } else if (idx < 1920) {
                int j = idx - 640;
                int row = j >> 5, seg = j & 31;
                cpasync16(bb + (uint32_t)((20 + row) * 528 + seg * 16),
                          hf + (size_t)(br * SL_H + row) * LSTM + kc + seg * 4);
            }
        }
        asm volatile("cp.async.commit_group;" ::: "memory");
    };

    {
        const float* esrc = emb + (size_t)br * (SL_H * WE);
        for (int i = t; i < 3000; i += 256)
            cpasync16(smem_base + (uint32_t)(i * 16), esrc + i * 4);
    }
    load_chunk(0);

    const int q2 = t / 20;
    const int h2 = t % 20;
    float acc00 = 0.f, acc01 = 0.f, acc10 = 0.f, acc11 = 0.f;

    for (int c = 0; c < 8; c++) {
        if (c + 1 < 8) {
            load_chunk(c + 1);
            asm volatile("cp.async.wait_group 1;" ::: "memory");
        } else {
            asm volatile("cp.async.wait_group 0;" ::: "memory");
        }
        __syncthreads();
        if (t < 200) {
            const float* base = sm + A2_BUF + (c & 1) * A2_BUFW;
            const float4* q0p = (const float4*)(base + (2 * q2) * 132);
            const float4* q1p = (const float4*)(base + (2 * q2 + 1) * 132);
            const float4* h0p = (const float4*)(base + (20 + 2 * h2) * 132);
            const float4* h1p = (const float4*)(base + (20 + 2 * h2 + 1) * 132);
#pragma unroll 8
            for (int k = 0; k < 32; k++) {
                float4 q0 = q0p[k], q1 = q1p[k];
                float4 h0 = h0p[k], h1 = h1p[k];
                acc00 += q0.x * h0.x + q0.y * h0.y + q0.z * h0.z + q0.w * h0.w;
                acc01 += q0.x * h1.x + q0.y * h1.y + q0.z * h1.z + q0.w * h1.w;
                acc10 += q1.x * h0.x + q1.y * h0.y + q1.z * h0.z + q1.w * h0.w;
                acc11 += q1.x * h1.x + q1.y * h1.y + q1.z * h1.z + q1.w * h1.w;
            }
        }
        __syncthreads();
    }

    float* S = sm + A2_S;
    if (t < 200) {
        S[(2 * q2)     * SL_H + 2 * h2]     = acc00;
        S[(2 * q2)     * SL_H + 2 * h2 + 1] = acc01;
        S[(2 * q2 + 1) * SL_H + 2 * h2]     = acc10;
        S[(2 * q2 + 1) * SL_H + 2 * h2 + 1] = acc11;
    }
    __syncthreads();

    if (t < SL_Q) {
        float mx = -1e30f;
        for (int h = 0; h < SL_H; h++) {
            float m = notpad[(size_t)br * SL_H + h];
            float s = S[t * SL_H + h] * m + (m - 1.0f) * 10000.0f;
            S[t * SL_H + h] = s;
            mx = fmaxf(mx, s);
        }
        float den = 0.f;
        for (int h = 0; h < SL_H; h++) {
            float e = expf(S[t * SL_H + h] - mx);
            S[t * SL_H + h] = e;
            den += e;
        }
        float inv = 1.0f / den;
        for (int h = 0; h < SL_H; h++) S[t * SL_H + h] *= inv;
    }
    __syncthreads();

    const float cmsv = cms[br];
    for (int task = t; task < SL_Q * 75; task += 256) {
        int q = task / 75, eg = task % 75;
        const float* ss = S + q * SL_H;
        float ax = 0.f, ay = 0.f, az = 0.f, aw = 0.f;
#pragma unroll 8
        for (int h = 0; h < SL_H; h++) {
            float a = ss[h];
            float4 e4 = *(const float4*)(sm + h * WE + eg * 4);
            ax += a * e4.x; ay += a * e4.y; az += a * e4.z; aw += a * e4.w;
        }
        float4 o = make_float4(ax * cmsv, ay * cmsv, az * cmsv, aw * cmsv);
        *(float4*)&topic[(size_t)(br * SL_Q + q) * WE + eg * 4] = o;
    }
}

// ---------------------------------------------------------------------------
// Kernel 3: feat = concat(q_embed, sum_r topic)
// ---------------------------------------------------------------------------
__global__ __launch_bounds__(256)
void feat_build(const float* __restrict__ q_embed, const float* __restrict__ topic,
                float* __restrict__ feat) {
    int idx = blockIdx.x * 256 + threadIdx.x;
    int m  = idx / FEATD;
    int e2 = idx % FEATD;
    float v;
    if (e2 < WE) {
        v = q_embed[(size_t)m * WE + e2];
    } else {
        int e = e2 - WE;
        int b = m / SL_Q, q = m % SL_Q;
        v = 0.f;
#pragma unroll
        for (int r = 0; r < NUM_R; r++)
            v += topic[(size_t)((b * NUM_R + r) * SL_Q + q) * WE + e];
    }
    feat[idx] = v;
}

// ---------------------------------------------------------------------------
// Kernel 4: out = sigmoid(feat@Wg + bg) * feat
// ---------------------------------------------------------------------------
#define FBM 64
#define FBN 64
#define FBK 16

__global__ __launch_bounds__(256)
void final_gemm(const float* __restrict__ feat, const float* __restrict__ Wg,
                const float* __restrict__ bg, float* __restrict__ out) {
    __shared__ float Fs[FBM][FBK + 1];
    __shared__ float Bsm[FBK][FBN + 1];

    const int t = threadIdx.x;
    const int ty = t >> 4, tx = t & 15;
    const int m0 = blockIdx.x * FBM;
    const int n0 = blockIdx.y * FBN;

    float acc[4][4];
#pragma unroll
    for (int i = 0; i < 4; i++)
#pragma unroll
        for (int j = 0; j < 4; j++) acc[i][j] = 0.f;

    for (int k0 = 0; k0 < FEATD; k0 += FBK) {
        for (int i = t; i < FBM * FBK; i += 256) {
            int r = i >> 4, c = i & 15;
            int k = k0 + c;
            Fs[r][c] = (k < FEATD) ? feat[(size_t)(m0 + r) * FEATD + k] : 0.f;
        }
        for (int i = t; i < FBK * FBN; i += 256) {
            int r = i >> 6, c = i & 63;
            int k = k0 + r, n = n0 + c;
            Bsm[r][c] = (k < FEATD && n < FEATD) ? Wg[(size_t)k * FEATD + n] : 0.f;
        }
        __syncthreads();
#pragma unroll
        for (int k = 0; k < FBK; k++) {
            float a[4], bb[4];
#pragma unroll
            for (int i = 0; i < 4; i++) a[i]  = Fs[ty * 4 + i][k];
#pragma unroll
            for (int j = 0; j < 4; j++) bb[j] = Bsm[k][tx * 4 + j];
#pragma unroll
            for (int i = 0; i < 4; i++)
#pragma unroll
                for (int j = 0; j < 4; j++) acc[i][j] += a[i] * bb[j];
        }
        __syncthreads();
    }

#pragma unroll
    for (int i = 0; i < 4; i++) {
        int row = m0 + ty * 4 + i;
#pragma unroll
        for (int j = 0; j < 4; j++) {
            int col = n0 + tx * 4 + j;
            if (col < FEATD) {
                float v = acc[i][j] + bg[col];
                float g = 1.0f / (1.0f + expf(-v));
                out[(size_t)row * FEATD + col] = g * feat[(size_t)row * FEATD + col];
            }
        }
    }
}

// ---------------------------------------------------------------------------
// Host launcher
// ---------------------------------------------------------------------------
extern "C" void kernel_launch(void* const* d_in, const int* in_sizes, int n_in,
                              void* d_out, int out_size) {
    const float* q_embed = (const float*)d_in[0];
    const float* q_enc   = (const float*)d_in[1];
    const float* h_embed = (const float*)d_in[2];
    const float* h_enc   = (const float*)d_in[3];
    const float* notpad  = (const float*)d_in[4];
    const float* cms     = (const float*)d_in[5];
    const float* Wq_y = (const float*)d_in[6];
    const float* bq_y = (const float*)d_in[7];
    const float* Wq_g = (const float*)d_in[8];
    const float* bq_g = (const float*)d_in[9];
    const float* Wh_y = (const float*)d_in[10];
    const float* bh_y = (const float*)d_in[11];
    const float* Wh_g = (const float*)d_in[12];
    const float* bh_g = (const float*)d_in[13];
    const float* Wg   = (const float*)d_in[14];
    const float* bg   = (const float*)d_in[15];
    float* out = (float*)d_out;

    float *qf, *hf, *topic, *feat;
    cudaGetSymbolAddress((void**)&qf,    g_qfeat);
    cudaGetSymbolAddress((void**)&hf,    g_hfeat);
    cudaGetSymbolAddress((void**)&topic, g_topic);
    cudaGetSymbolAddress((void**)&feat,  g_feat);

    uint32_t *xq_h, *xq_l, *xh_h, *xh_l;
    uint32_t *wqy_h, *wqy_l, *wqg_h, *wqg_l, *why_h, *why_l, *whg_h, *whg_l;
    cudaGetSymbolAddress((void**)&xq_h, g_xq_h);
    cudaGetSymbolAddress((void**)&xq_l, g_xq_l);
    cudaGetSymbolAddress((void**)&xh_h, g_xh_h);
    cudaGetSymbolAddress((void**)&xh_l, g_xh_l);
    cudaGetSymbolAddress((void**)&wqy_h, g_wqy_h);
    cudaGetSymbolAddress((void**)&wqy_l, g_wqy_l);
    cudaGetSymbolAddress((void**)&wqg_h, g_wqg_h);
    cudaGetSymbolAddress((void**)&wqg_l, g_wqg_l);
    cudaGetSymbolAddress((void**)&why_h, g_why_h);
    cudaGetSymbolAddress((void**)&why_l, g_why_l);
    cudaGetSymbolAddress((void**)&whg_h, g_whg_h);
    cudaGetSymbolAddress((void**)&whg_l, g_whg_l);

    cudaFuncSetAttribute(gated_gemm_all, cudaFuncAttributeMaxDynamicSharedMemorySize,
                         GG_SMEM);
    cudaFuncSetAttribute(attn_v2, cudaFuncAttributeMaxDynamicSharedMemorySize,
                         A2_FLOATS * (int)sizeof(float));

    // 0: fused X splits
    {
        int n4 = (MQ + MH) * BILSTM / 4;
        split_x_all<<<(n4 + 255) / 256, 256>>>(q_enc, xq_h, xq_l, h_enc, xh_h, xh_l);
    }
    // 1: fused transposed W splits
    {
        dim3 wg(BILSTM / 32, LSTM / 32, 4);
        split_wt_all<<<wg, 256>>>(Wq_y, wqy_h, wqy_l, Wq_g, wqg_h, wqg_l,
                                  Wh_y, why_h, why_l, Wh_g, whg_h, whg_l);
    }
    // 2: merged gated transforms (R8 proven config)
    gated_gemm_all<<<dim3(LSTM / TBN, 5 + MH / TBM), 256, GG_SMEM>>>(
        xq_h, xq_l, wqy_h, wqy_l, wqg_h, wqg_l, bq_y, bq_g, qf,
        xh_h, xh_l, why_h, why_l, whg_h, whg_l, bh_y, bh_g, hf);

    // 3: attention + topic (proven attn_v2)
    attn_v2<<<dim3(NUM_R, BS), 256, A2_FLOATS * (int)sizeof(float)>>>(
        qf, hf, h_embed, notpad, cms, topic);

    // 4: concat + reduce over r
    feat_build<<<(MQ * FEATD) / 256, 256>>>(q_embed, topic, feat);

    // 5: final gated output
    final_gemm<<<dim3(MQ / FBM, (FEATD + FBN - 1) / FBN), 256>>>(feat, Wg, bg, out);
}